// round 1
// baseline (speedup 1.0000x reference)
#include <cuda_runtime.h>
#include <cstdint>

// Problem constants (match reference)
#define NN 50000
#define EE 800000
#define HID 256
#define HEADS 8
#define CPH 32
#define EDIM 64

// ---------------- scratch (device globals; no allocation allowed) ----------
__device__ float    g_xp   [(size_t)NN * HID];   // x @ W
__device__ float    g_num  [(size_t)NN * HID];   // sum ea * xp[src]
__device__ float    g_alpha[(size_t)EE * HEADS]; // post-leakyrelu logits
__device__ float    g_asrc [(size_t)NN * HEADS];
__device__ float    g_adst [(size_t)NN * HEADS];
__device__ float    g_den  [(size_t)NN * HEADS];
__device__ unsigned g_menc [(size_t)NN * HEADS]; // encoded float max
__device__ float    g_watt [EDIM * HEADS];

// monotone float<->uint encoding for atomicMax on signed floats
__device__ __forceinline__ unsigned enc_f(float f) {
    unsigned u = __float_as_uint(f);
    return (u & 0x80000000u) ? ~u : (u | 0x80000000u);
}
__device__ __forceinline__ float dec_f(unsigned u) {
    u = (u & 0x80000000u) ? (u & 0x7FFFFFFFu) : ~u;
    return __uint_as_float(u);
}

__device__ __forceinline__ void red_add_v4(float* p, float4 v) {
    asm volatile("red.global.add.v4.f32 [%0], {%1,%2,%3,%4};"
                 :: "l"(p), "f"(v.x), "f"(v.y), "f"(v.z), "f"(v.w) : "memory");
}

// ---------------- init: zero accumulators --------------------------------
__global__ void init_scratch() {
    size_t stride = (size_t)gridDim.x * blockDim.x;
    for (size_t i = (size_t)blockIdx.x * blockDim.x + threadIdx.x;
         i < (size_t)NN * HID; i += stride) {
        g_num[i] = 0.f;
        if (i < (size_t)NN * HEADS) { g_den[i] = 0.f; g_menc[i] = 0u; }
    }
}

// ---------------- w_att = fold(W_e, att_edge) -----------------------------
__global__ void compute_watt(const float* __restrict__ W_e,
                             const float* __restrict__ att_edge) {
    int i = threadIdx.x;              // 512 threads
    int d = i >> 3, h = i & 7;
    float s = 0.f;
    #pragma unroll
    for (int c = 0; c < CPH; c++)
        s += W_e[d * (HEADS * CPH) + h * CPH + c] * att_edge[h * CPH + c];
    g_watt[d * HEADS + h] = s;
}

// ---------------- xp = x @ W  (128x64 tile SGEMM) --------------------------
#define BM 128
#define BN 64
#define BK 16
__global__ __launch_bounds__(256) void sgemm_xW(const float* __restrict__ A,
                                                const float* __restrict__ B) {
    __shared__ float As[BK][BM + 4];
    __shared__ float Bs[BK][BN];
    const int K = HID, Nc = HID;
    int bm = blockIdx.y * BM;
    int bn = blockIdx.x * BN;
    int tid = threadIdx.x;
    int tx = tid & 15;   // 4 cols each
    int ty = tid >> 4;   // 8 rows each
    float acc[8][4];
    #pragma unroll
    for (int i = 0; i < 8; i++)
        #pragma unroll
        for (int j = 0; j < 4; j++) acc[i][j] = 0.f;

    for (int k0 = 0; k0 < K; k0 += BK) {
        #pragma unroll
        for (int l = 0; l < 8; l++) {
            int row = l * 16 + (tid >> 4);
            int col = tid & 15;
            int gr = bm + row;
            float v = (gr < NN) ? A[(size_t)gr * K + k0 + col] : 0.f;
            As[col][row] = v;
        }
        #pragma unroll
        for (int l = 0; l < 4; l++) {
            int idx = l * 256 + tid;
            int row = idx >> 6;
            int col = idx & 63;
            Bs[row][col] = B[(size_t)(k0 + row) * Nc + bn + col];
        }
        __syncthreads();
        #pragma unroll
        for (int k = 0; k < BK; k++) {
            float a[8], b[4];
            #pragma unroll
            for (int i = 0; i < 8; i++) a[i] = As[k][ty * 8 + i];
            #pragma unroll
            for (int j = 0; j < 4; j++) b[j] = Bs[k][tx * 4 + j];
            #pragma unroll
            for (int i = 0; i < 8; i++)
                #pragma unroll
                for (int j = 0; j < 4; j++) acc[i][j] += a[i] * b[j];
        }
        __syncthreads();
    }
    #pragma unroll
    for (int i = 0; i < 8; i++) {
        int gr = bm + ty * 8 + i;
        if (gr < NN) {
            #pragma unroll
            for (int j = 0; j < 4; j++)
                g_xp[(size_t)gr * Nc + bn + tx * 4 + j] = acc[i][j];
        }
    }
}

// ---------------- per-node attention coefficients -------------------------
__global__ void node_att(const float* __restrict__ att_src,
                         const float* __restrict__ att_dst) {
    int warp = (blockIdx.x * blockDim.x + threadIdx.x) >> 5;
    int lane = threadIdx.x & 31;
    if (warp >= NN) return;
    const float* row = g_xp + (size_t)warp * HID;
    #pragma unroll
    for (int h = 0; h < HEADS; h++) {
        float v = row[h * CPH + lane];
        float s = v * att_src[h * CPH + lane];
        float d = v * att_dst[h * CPH + lane];
        #pragma unroll
        for (int o = 16; o > 0; o >>= 1) {
            s += __shfl_xor_sync(0xffffffffu, s, o);
            d += __shfl_xor_sync(0xffffffffu, d, o);
        }
        if (lane == 0) {
            g_asrc[(size_t)warp * HEADS + h] = s;
            g_adst[(size_t)warp * HEADS + h] = d;
        }
    }
}

// ---------------- edge pass 1: logits + segment max -----------------------
__global__ __launch_bounds__(256) void edge_pass1(const int* __restrict__ ei,
                                                  const float* __restrict__ eattr) {
    __shared__ float ws[EDIM * HEADS];
    for (int i = threadIdx.x; i < EDIM * HEADS; i += blockDim.x) ws[i] = g_watt[i];
    __syncthreads();
    int e = blockIdx.x * blockDim.x + threadIdx.x;
    if (e >= EE) return;
    int src = ei[e];
    int dst = ei[EE + e];

    const float4* as4 = (const float4*)(g_asrc + (size_t)src * HEADS);
    const float4* ad4 = (const float4*)(g_adst + (size_t)dst * HEADS);
    float4 as0 = as4[0], as1 = as4[1];
    float4 ad0 = ad4[0], ad1 = ad4[1];

    float acc[HEADS];
    #pragma unroll
    for (int h = 0; h < HEADS; h++) acc[h] = 0.f;

    const float4* ea4 = (const float4*)(eattr + (size_t)e * EDIM);
    #pragma unroll
    for (int d4 = 0; d4 < EDIM / 4; d4++) {
        float4 v = ea4[d4];
        int d = d4 * 4;
        #pragma unroll
        for (int h = 0; h < HEADS; h++) acc[h] += v.x * ws[(d + 0) * HEADS + h];
        #pragma unroll
        for (int h = 0; h < HEADS; h++) acc[h] += v.y * ws[(d + 1) * HEADS + h];
        #pragma unroll
        for (int h = 0; h < HEADS; h++) acc[h] += v.z * ws[(d + 2) * HEADS + h];
        #pragma unroll
        for (int h = 0; h < HEADS; h++) acc[h] += v.w * ws[(d + 3) * HEADS + h];
    }

    float a[HEADS];
    a[0] = as0.x + ad0.x + acc[0];
    a[1] = as0.y + ad0.y + acc[1];
    a[2] = as0.z + ad0.z + acc[2];
    a[3] = as0.w + ad0.w + acc[3];
    a[4] = as1.x + ad1.x + acc[4];
    a[5] = as1.y + ad1.y + acc[5];
    a[6] = as1.z + ad1.z + acc[6];
    a[7] = as1.w + ad1.w + acc[7];

    #pragma unroll
    for (int h = 0; h < HEADS; h++) {
        float al = a[h];
        al = (al > 0.f) ? al : 0.2f * al;   // LeakyReLU
        a[h] = al;
        atomicMax(&g_menc[(size_t)dst * HEADS + h], enc_f(al));
    }
    float4* alp = (float4*)(g_alpha + (size_t)e * HEADS);
    alp[0] = make_float4(a[0], a[1], a[2], a[3]);
    alp[1] = make_float4(a[4], a[5], a[6], a[7]);
}

// ---------------- edge pass 2: exp + den + weighted scatter ----------------
__global__ __launch_bounds__(256) void edge_pass2(const int* __restrict__ ei) {
    int e = (blockIdx.x * blockDim.x + threadIdx.x) >> 5;
    int lane = threadIdx.x & 31;
    if (e >= EE) return;
    int src = 0, dst = 0;
    if (lane == 0) { src = ei[e]; dst = ei[EE + e]; }
    src = __shfl_sync(0xffffffffu, src, 0);
    dst = __shfl_sync(0xffffffffu, dst, 0);

    float myea = 0.f;
    if (lane < HEADS) {
        float al = g_alpha[(size_t)e * HEADS + lane];
        float mm = dec_f(g_menc[(size_t)dst * HEADS + lane]);
        myea = __expf(al - mm);
        atomicAdd(&g_den[(size_t)dst * HEADS + lane], myea);
    }
    float ea0 = __shfl_sync(0xffffffffu, myea, lane >> 3);
    float ea1 = __shfl_sync(0xffffffffu, myea, 4 + (lane >> 3));

    const float4* xp4 = (const float4*)(g_xp) + (size_t)src * (HID / 4);
    float4 g0 = xp4[lane];
    float4 g1 = xp4[32 + lane];
    float4 r0 = make_float4(g0.x * ea0, g0.y * ea0, g0.z * ea0, g0.w * ea0);
    float4 r1 = make_float4(g1.x * ea1, g1.y * ea1, g1.z * ea1, g1.w * ea1);

    float* base = g_num + (size_t)dst * HID + lane * 4;
    red_add_v4(base, r0);
    red_add_v4(base + 128, r1);
}

// ---------------- final: normalize + residual + LayerNorm ------------------
__global__ __launch_bounds__(256) void final_ln(const float* __restrict__ x,
                                                const float* __restrict__ bias,
                                                const float* __restrict__ gamma,
                                                const float* __restrict__ beta,
                                                float* __restrict__ out) {
    int n = blockIdx.x;
    int c = threadIdx.x;
    __shared__ float sden[HEADS];
    __shared__ float ssum[8], ssq[8];
    __shared__ float smu, srstd;
    if (c < HEADS) sden[c] = g_den[(size_t)n * HEADS + c] + 1e-16f;
    __syncthreads();
    float v = x[(size_t)n * HID + c] + g_num[(size_t)n * HID + c] / sden[c >> 5] + bias[c];
    float s = v, q = v * v;
    #pragma unroll
    for (int o = 16; o > 0; o >>= 1) {
        s += __shfl_xor_sync(0xffffffffu, s, o);
        q += __shfl_xor_sync(0xffffffffu, q, o);
    }
    int w = c >> 5, l = c & 31;
    if (l == 0) { ssum[w] = s; ssq[w] = q; }
    __syncthreads();
    if (c == 0) {
        float ts = 0.f, tq = 0.f;
        #pragma unroll
        for (int i = 0; i < 8; i++) { ts += ssum[i]; tq += ssq[i]; }
        float mu = ts * (1.f / HID);
        float var = tq * (1.f / HID) - mu * mu;
        smu = mu;
        srstd = rsqrtf(var + 1e-5f);
    }
    __syncthreads();
    out[(size_t)n * HID + c] = (v - smu) * srstd * gamma[c] + beta[c];
}

// ---------------- launch ----------------------------------------------------
extern "C" void kernel_launch(void* const* d_in, const int* in_sizes, int n_in,
                              void* d_out, int out_size) {
    const float* x        = (const float*)d_in[0];
    const int*   ei       = (const int*)  d_in[1];
    const float* eattr    = (const float*)d_in[2];
    const float* W        = (const float*)d_in[3];
    const float* W_e      = (const float*)d_in[4];
    const float* att_src  = (const float*)d_in[5];
    const float* att_dst  = (const float*)d_in[6];
    const float* att_edge = (const float*)d_in[7];
    const float* bias     = (const float*)d_in[8];
    const float* gamma    = (const float*)d_in[9];
    const float* beta     = (const float*)d_in[10];
    float* out = (float*)d_out;

    init_scratch<<<4096, 256>>>();
    compute_watt<<<1, EDIM * HEADS>>>(W_e, att_edge);

    dim3 ggrid(HID / BN, (NN + BM - 1) / BM);
    sgemm_xW<<<ggrid, 256>>>(x, W);

    node_att<<<(NN * 32 + 255) / 256, 256>>>(att_src, att_dst);

    edge_pass1<<<(EE + 255) / 256, 256>>>(ei, eattr);
    edge_pass2<<<(EE * 32 + 255) / 256, 256>>>(ei);

    final_ln<<<NN, HID>>>(x, bias, gamma, beta, out);
}

// round 2
// speedup vs baseline: 1.1254x; 1.1254x over previous
#include <cuda_runtime.h>
#include <cstdint>

#define NN 50000
#define EE 800000
#define HID 256
#define HEADS 8
#define CPH 32
#define EDIM 64

// ---------------- scratch ----------------
__device__ float g_xp  [(size_t)NN * HID];   // x @ W
__device__ float g_ea  [(size_t)EE * HEADS]; // exp(leakyrelu(logit))
__device__ float g_asrc[(size_t)NN * HEADS];
__device__ float g_adst[(size_t)NN * HEADS];
__device__ float g_watt[EDIM * HEADS];
__device__ int   g_deg [NN];
__device__ int   g_start[NN];
__device__ int   g_cur [NN];
__device__ int   g_csr_src[EE];
__device__ int   g_csr_eid[EE];

// ---------------- zero degree counters ----------------
__global__ void zero_deg() {
    int i = blockIdx.x * blockDim.x + threadIdx.x;
    if (i < NN) g_deg[i] = 0;
}

// ---------------- fold W_e with att_edge ----------------
__global__ void compute_watt(const float* __restrict__ W_e,
                             const float* __restrict__ att_edge) {
    int i = threadIdx.x;              // 512 threads
    int d = i >> 3, h = i & 7;
    float s = 0.f;
    #pragma unroll
    for (int c = 0; c < CPH; c++)
        s += W_e[d * (HEADS * CPH) + h * CPH + c] * att_edge[h * CPH + c];
    g_watt[d * HEADS + h] = s;
}

// ---------------- CSR build ----------------
__global__ void count_deg(const int* __restrict__ ei) {
    int e = blockIdx.x * blockDim.x + threadIdx.x;
    if (e < EE) atomicAdd(&g_deg[ei[EE + e]], 1);
}

__global__ __launch_bounds__(1024) void scan_deg() {
    __shared__ int sp[1024];
    const int CH = 49;  // 1024*49 = 50176 >= NN
    int t = threadIdx.x;
    int base = t * CH;
    int s = 0;
    for (int i = 0; i < CH; i++) {
        int idx = base + i;
        if (idx < NN) s += g_deg[idx];
    }
    sp[t] = s;
    __syncthreads();
    for (int o = 1; o < 1024; o <<= 1) {
        int v = (t >= o) ? sp[t - o] : 0;
        __syncthreads();
        sp[t] += v;
        __syncthreads();
    }
    int run = (t > 0) ? sp[t - 1] : 0;
    for (int i = 0; i < CH; i++) {
        int idx = base + i;
        if (idx < NN) {
            g_start[idx] = run;
            g_cur[idx]   = run;
            run += g_deg[idx];
        }
    }
}

__global__ void scatter_csr(const int* __restrict__ ei) {
    int e = blockIdx.x * blockDim.x + threadIdx.x;
    if (e >= EE) return;
    int src = ei[e];
    int dst = ei[EE + e];
    int pos = atomicAdd(&g_cur[dst], 1);
    g_csr_src[pos] = src;
    g_csr_eid[pos] = e;
}

// ---------------- xp = x @ W : 128x128x8 SGEMM, 8x8 per thread -------------
#define GM 128
#define GN 128
#define GK 8
__global__ __launch_bounds__(256, 2) void sgemm_xW(const float* __restrict__ A,
                                                   const float* __restrict__ B) {
    __shared__ float As[GK][GM];
    __shared__ float Bs[GK][GN];
    int bm = blockIdx.y * GM;
    int bn = blockIdx.x * GN;
    int t = threadIdx.x;
    int tx = t & 15;       // col block  tx*8
    int ty = t >> 4;       // row block  ty*8
    int arow = t >> 1, aseg = (t & 1) * 4;
    int brow = t >> 5, bcol = (t & 31) * 4;

    float acc[8][8];
    #pragma unroll
    for (int i = 0; i < 8; i++)
        #pragma unroll
        for (int j = 0; j < 8; j++) acc[i][j] = 0.f;

    for (int k0 = 0; k0 < HID; k0 += GK) {
        float4 av = make_float4(0.f, 0.f, 0.f, 0.f);
        if (bm + arow < NN)
            av = *(const float4*)(A + (size_t)(bm + arow) * HID + k0 + aseg);
        As[aseg + 0][arow] = av.x;
        As[aseg + 1][arow] = av.y;
        As[aseg + 2][arow] = av.z;
        As[aseg + 3][arow] = av.w;
        *(float4*)(&Bs[brow][bcol]) =
            *(const float4*)(B + (size_t)(k0 + brow) * HID + bn + bcol);
        __syncthreads();
        #pragma unroll
        for (int k = 0; k < GK; k++) {
            float a[8], b[8];
            *(float4*)(a)     = *(float4*)(&As[k][ty * 8]);
            *(float4*)(a + 4) = *(float4*)(&As[k][ty * 8 + 4]);
            *(float4*)(b)     = *(float4*)(&Bs[k][tx * 8]);
            *(float4*)(b + 4) = *(float4*)(&Bs[k][tx * 8 + 4]);
            #pragma unroll
            for (int i = 0; i < 8; i++)
                #pragma unroll
                for (int j = 0; j < 8; j++) acc[i][j] += a[i] * b[j];
        }
        __syncthreads();
    }
    #pragma unroll
    for (int i = 0; i < 8; i++) {
        int r = bm + ty * 8 + i;
        if (r < NN) {
            float* dst = g_xp + (size_t)r * HID + bn + tx * 8;
            *(float4*)(dst)     = *(float4*)(&acc[i][0]);
            *(float4*)(dst + 4) = *(float4*)(&acc[i][4]);
        }
    }
}

// ---------------- per-node attention coefficients (vectorized) ------------
__global__ void node_att(const float* __restrict__ att_src,
                         const float* __restrict__ att_dst) {
    int n = (blockIdx.x * blockDim.x + threadIdx.x) >> 5;
    int lane = threadIdx.x & 31;
    if (n >= NN) return;
    const float4* row = (const float4*)g_xp + (size_t)n * (HID / 4);
    float4 v0 = row[lane], v1 = row[32 + lane];
    const float4* s4 = (const float4*)att_src;
    const float4* d4 = (const float4*)att_dst;
    float4 sa = s4[lane], sb = s4[32 + lane];
    float4 da = d4[lane], db = d4[32 + lane];
    float ps0 = v0.x * sa.x + v0.y * sa.y + v0.z * sa.z + v0.w * sa.w;
    float pd0 = v0.x * da.x + v0.y * da.y + v0.z * da.z + v0.w * da.w;
    float ps1 = v1.x * sb.x + v1.y * sb.y + v1.z * sb.z + v1.w * sb.w;
    float pd1 = v1.x * db.x + v1.y * db.y + v1.z * db.z + v1.w * db.w;
    #pragma unroll
    for (int o = 4; o >= 1; o >>= 1) {
        ps0 += __shfl_xor_sync(0xffffffffu, ps0, o);
        pd0 += __shfl_xor_sync(0xffffffffu, pd0, o);
        ps1 += __shfl_xor_sync(0xffffffffu, ps1, o);
        pd1 += __shfl_xor_sync(0xffffffffu, pd1, o);
    }
    if ((lane & 7) == 0) {
        int h = lane >> 3;   // channels lane*4 .. -> head lane>>3
        g_asrc[(size_t)n * HEADS + h]     = ps0;
        g_asrc[(size_t)n * HEADS + 4 + h] = ps1;
        g_adst[(size_t)n * HEADS + h]     = pd0;
        g_adst[(size_t)n * HEADS + 4 + h] = pd1;
    }
}

// ---------------- edge pass: logits -> leakyrelu -> exp (no max!) ----------
__global__ __launch_bounds__(256) void edge_ea(const int* __restrict__ ei,
                                               const float* __restrict__ eattr) {
    __shared__ float ws[EDIM * HEADS];
    for (int i = threadIdx.x; i < EDIM * HEADS; i += blockDim.x) ws[i] = g_watt[i];
    __syncthreads();
    int e = blockIdx.x * blockDim.x + threadIdx.x;
    if (e >= EE) return;
    int src = ei[e];
    int dst = ei[EE + e];

    const float4* as4 = (const float4*)(g_asrc + (size_t)src * HEADS);
    const float4* ad4 = (const float4*)(g_adst + (size_t)dst * HEADS);
    float4 as0 = as4[0], as1 = as4[1];
    float4 ad0 = ad4[0], ad1 = ad4[1];

    float acc[HEADS];
    #pragma unroll
    for (int h = 0; h < HEADS; h++) acc[h] = 0.f;

    const float4* ea4 = (const float4*)(eattr + (size_t)e * EDIM);
    #pragma unroll
    for (int d4 = 0; d4 < EDIM / 4; d4++) {
        float4 v = ea4[d4];
        int d = d4 * 4;
        #pragma unroll
        for (int h = 0; h < HEADS; h++) acc[h] += v.x * ws[(d + 0) * HEADS + h];
        #pragma unroll
        for (int h = 0; h < HEADS; h++) acc[h] += v.y * ws[(d + 1) * HEADS + h];
        #pragma unroll
        for (int h = 0; h < HEADS; h++) acc[h] += v.z * ws[(d + 2) * HEADS + h];
        #pragma unroll
        for (int h = 0; h < HEADS; h++) acc[h] += v.w * ws[(d + 3) * HEADS + h];
    }

    float a[HEADS];
    a[0] = as0.x + ad0.x + acc[0];
    a[1] = as0.y + ad0.y + acc[1];
    a[2] = as0.z + ad0.z + acc[2];
    a[3] = as0.w + ad0.w + acc[3];
    a[4] = as1.x + ad1.x + acc[4];
    a[5] = as1.y + ad1.y + acc[5];
    a[6] = as1.z + ad1.z + acc[6];
    a[7] = as1.w + ad1.w + acc[7];

    #pragma unroll
    for (int h = 0; h < HEADS; h++) {
        float al = a[h];
        al = (al > 0.f) ? al : 0.2f * al;   // LeakyReLU
        a[h] = __expf(al);                  // direct exp: softmax is shift-invariant
    }
    float4* out = (float4*)(g_ea + (size_t)e * HEADS);
    out[0] = make_float4(a[0], a[1], a[2], a[3]);
    out[1] = make_float4(a[4], a[5], a[6], a[7]);
}

// ---------------- aggregate (gather) + residual + LayerNorm ----------------
__global__ __launch_bounds__(256) void aggregate(const float* __restrict__ x,
                                                 const float* __restrict__ bias,
                                                 const float* __restrict__ gamma,
                                                 const float* __restrict__ beta,
                                                 float* __restrict__ out) {
    int n = (blockIdx.x * blockDim.x + threadIdx.x) >> 5;
    int lane = threadIdx.x & 31;
    if (n >= NN) return;
    int start = g_start[n];
    int deg   = g_deg[n];
    int ha = lane >> 3;        // head for channels lane*4..lane*4+3
    int hb = 4 + (lane >> 3);  // head for channels 128+lane*4..

    float4 acc_a = make_float4(0.f, 0.f, 0.f, 0.f);
    float4 acc_b = make_float4(0.f, 0.f, 0.f, 0.f);
    float den = 0.f;

    for (int i = 0; i < deg; i++) {
        int p = start + i;
        int src = g_csr_src[p];
        int eid = g_csr_eid[p];
        float eav = 0.f;
        if (lane < 8) eav = g_ea[(size_t)eid * HEADS + lane];
        den += eav;
        float ea_a = __shfl_sync(0xffffffffu, eav, ha);
        float ea_b = __shfl_sync(0xffffffffu, eav, hb);
        const float4* xp4 = (const float4*)g_xp + (size_t)src * (HID / 4);
        float4 g0 = xp4[lane];
        float4 g1 = xp4[32 + lane];
        acc_a.x += ea_a * g0.x; acc_a.y += ea_a * g0.y;
        acc_a.z += ea_a * g0.z; acc_a.w += ea_a * g0.w;
        acc_b.x += ea_b * g1.x; acc_b.y += ea_b * g1.y;
        acc_b.z += ea_b * g1.z; acc_b.w += ea_b * g1.w;
    }

    float inv = 1.f / (den + 1e-16f);    // lanes 0..7 hold per-head den
    float inv_a = __shfl_sync(0xffffffffu, inv, ha);
    float inv_b = __shfl_sync(0xffffffffu, inv, hb);

    const float4* x4 = (const float4*)x + (size_t)n * (HID / 4);
    float4 xa = x4[lane], xb = x4[32 + lane];
    float4 ba = ((const float4*)bias)[lane];
    float4 bb = ((const float4*)bias)[32 + lane];

    float4 va, vb;
    va.x = xa.x + acc_a.x * inv_a + ba.x;
    va.y = xa.y + acc_a.y * inv_a + ba.y;
    va.z = xa.z + acc_a.z * inv_a + ba.z;
    va.w = xa.w + acc_a.w * inv_a + ba.w;
    vb.x = xb.x + acc_b.x * inv_b + bb.x;
    vb.y = xb.y + acc_b.y * inv_b + bb.y;
    vb.z = xb.z + acc_b.z * inv_b + bb.z;
    vb.w = xb.w + acc_b.w * inv_b + bb.w;

    float s = va.x + va.y + va.z + va.w + vb.x + vb.y + vb.z + vb.w;
    float q = va.x * va.x + va.y * va.y + va.z * va.z + va.w * va.w
            + vb.x * vb.x + vb.y * vb.y + vb.z * vb.z + vb.w * vb.w;
    #pragma unroll
    for (int o = 16; o > 0; o >>= 1) {
        s += __shfl_xor_sync(0xffffffffu, s, o);
        q += __shfl_xor_sync(0xffffffffu, q, o);
    }
    float mu = s * (1.f / HID);
    float var = q * (1.f / HID) - mu * mu;
    float rstd = rsqrtf(var + 1e-5f);

    float4 ga = ((const float4*)gamma)[lane];
    float4 gb = ((const float4*)gamma)[32 + lane];
    float4 be = ((const float4*)beta)[lane];
    float4 bf = ((const float4*)beta)[32 + lane];

    float4 oa, ob;
    oa.x = (va.x - mu) * rstd * ga.x + be.x;
    oa.y = (va.y - mu) * rstd * ga.y + be.y;
    oa.z = (va.z - mu) * rstd * ga.z + be.z;
    oa.w = (va.w - mu) * rstd * ga.w + be.w;
    ob.x = (vb.x - mu) * rstd * gb.x + bf.x;
    ob.y = (vb.y - mu) * rstd * gb.y + bf.y;
    ob.z = (vb.z - mu) * rstd * gb.z + bf.z;
    ob.w = (vb.w - mu) * rstd * gb.w + bf.w;

    float4* o4 = (float4*)out + (size_t)n * (HID / 4);
    o4[lane] = oa;
    o4[32 + lane] = ob;
}

// ---------------- launch ----------------
extern "C" void kernel_launch(void* const* d_in, const int* in_sizes, int n_in,
                              void* d_out, int out_size) {
    const float* x        = (const float*)d_in[0];
    const int*   ei       = (const int*)  d_in[1];
    const float* eattr    = (const float*)d_in[2];
    const float* W        = (const float*)d_in[3];
    const float* W_e      = (const float*)d_in[4];
    const float* att_src  = (const float*)d_in[5];
    const float* att_dst  = (const float*)d_in[6];
    const float* att_edge = (const float*)d_in[7];
    const float* bias     = (const float*)d_in[8];
    const float* gamma    = (const float*)d_in[9];
    const float* beta     = (const float*)d_in[10];
    float* out = (float*)d_out;

    zero_deg<<<(NN + 255) / 256, 256>>>();
    compute_watt<<<1, EDIM * HEADS>>>(W_e, att_edge);
    count_deg<<<(EE + 255) / 256, 256>>>(ei);
    scan_deg<<<1, 1024>>>();
    scatter_csr<<<(EE + 255) / 256, 256>>>(ei);

    dim3 ggrid(HID / GN, (NN + GM - 1) / GM);
    sgemm_xW<<<ggrid, 256>>>(x, W);

    node_att<<<(NN * 32 + 255) / 256, 256>>>(att_src, att_dst);
    edge_ea<<<(EE + 255) / 256, 256>>>(ei, eattr);
    aggregate<<<(NN * 32 + 255) / 256, 256>>>(x, bias, gamma, beta, out);
}

// round 3
// speedup vs baseline: 1.4413x; 1.2806x over previous
#include <cuda_runtime.h>
#include <cstdint>

#define NN 50000
#define EE 800000
#define HID 256
#define HEADS 8
#define CPH 32
#define EDIM 64

// ---------------- scratch ----------------
__device__ float g_xp  [(size_t)NN * HID];   // x @ W
__device__ float g_ea  [(size_t)EE * HEADS]; // exp(leakyrelu(logit)), CSR order
__device__ float g_asrc[(size_t)NN * HEADS];
__device__ float g_adst[(size_t)NN * HEADS];
__device__ float g_watt[EDIM * HEADS];
__device__ int   g_deg [NN];
__device__ int   g_start[NN];
__device__ int   g_cur [NN];
__device__ int   g_csr_src[EE];
__device__ int   g_pos [EE];     // edge e -> CSR slot
__device__ int   g_total;

// ---------------- zero counters ----------------
__global__ void zero_deg() {
    int i = blockIdx.x * blockDim.x + threadIdx.x;
    if (i < NN) g_deg[i] = 0;
    if (i == 0) g_total = 0;
}

// ---------------- fold W_e with att_edge ----------------
__global__ void compute_watt(const float* __restrict__ W_e,
                             const float* __restrict__ att_edge) {
    int i = threadIdx.x;              // 512 threads
    int d = i >> 3, h = i & 7;
    float s = 0.f;
    #pragma unroll
    for (int c = 0; c < CPH; c++)
        s += W_e[d * (HEADS * CPH) + h * CPH + c] * att_edge[h * CPH + c];
    g_watt[d * HEADS + h] = s;
}

// ---------------- CSR build ----------------
__global__ void count_deg(const int* __restrict__ ei) {
    int e = blockIdx.x * blockDim.x + threadIdx.x;
    if (e < EE) atomicAdd(&g_deg[ei[EE + e]], 1);
}

// warp-scan + atomic region reservation (placement order is irrelevant)
__global__ void reserve_csr() {
    int n = blockIdx.x * blockDim.x + threadIdx.x;
    int lane = threadIdx.x & 31;
    int d = (n < NN) ? g_deg[n] : 0;
    int incl = d;
    #pragma unroll
    for (int o = 1; o < 32; o <<= 1) {
        int v = __shfl_up_sync(0xffffffffu, incl, o);
        if (lane >= o) incl += v;
    }
    int wtotal = __shfl_sync(0xffffffffu, incl, 31);
    int base = 0;
    if (lane == 31) base = atomicAdd(&g_total, wtotal);
    base = __shfl_sync(0xffffffffu, base, 31);
    int start = base + incl - d;
    if (n < NN) { g_start[n] = start; g_cur[n] = start; }
}

__global__ void scatter_csr(const int* __restrict__ ei) {
    int e = blockIdx.x * blockDim.x + threadIdx.x;
    if (e >= EE) return;
    int src = ei[e];
    int dst = ei[EE + e];
    int pos = atomicAdd(&g_cur[dst], 1);
    g_csr_src[pos] = src;
    g_pos[e] = pos;
}

// ---------------- xp = x @ W : 128x128x8 SGEMM + fused node_att epilogue ---
#define GM 128
#define GN 128
#define GK 8
__global__ __launch_bounds__(256, 2) void sgemm_xW(const float* __restrict__ A,
                                                   const float* __restrict__ B,
                                                   const float* __restrict__ att_src,
                                                   const float* __restrict__ att_dst) {
    __shared__ float As[GK][GM];
    __shared__ float Bs[GK][GN];
    int bm = blockIdx.y * GM;
    int bn = blockIdx.x * GN;
    int t = threadIdx.x;
    int tx = t & 15;       // col block  tx*8
    int ty = t >> 4;       // row block  ty*8
    int arow = t >> 1, aseg = (t & 1) * 4;
    int brow = t >> 5, bcol = (t & 31) * 4;

    float acc[8][8];
    #pragma unroll
    for (int i = 0; i < 8; i++)
        #pragma unroll
        for (int j = 0; j < 8; j++) acc[i][j] = 0.f;

    for (int k0 = 0; k0 < HID; k0 += GK) {
        float4 av = make_float4(0.f, 0.f, 0.f, 0.f);
        if (bm + arow < NN)
            av = *(const float4*)(A + (size_t)(bm + arow) * HID + k0 + aseg);
        As[aseg + 0][arow] = av.x;
        As[aseg + 1][arow] = av.y;
        As[aseg + 2][arow] = av.z;
        As[aseg + 3][arow] = av.w;
        *(float4*)(&Bs[brow][bcol]) =
            *(const float4*)(B + (size_t)(k0 + brow) * HID + bn + bcol);
        __syncthreads();
        #pragma unroll
        for (int k = 0; k < GK; k++) {
            float a[8], b[8];
            *(float4*)(a)     = *(float4*)(&As[k][ty * 8]);
            *(float4*)(a + 4) = *(float4*)(&As[k][ty * 8 + 4]);
            *(float4*)(b)     = *(float4*)(&Bs[k][tx * 8]);
            *(float4*)(b + 4) = *(float4*)(&Bs[k][tx * 8 + 4]);
            #pragma unroll
            for (int i = 0; i < 8; i++)
                #pragma unroll
                for (int j = 0; j < 8; j++) acc[i][j] += a[i] * b[j];
        }
        __syncthreads();
    }

    // att weights for this thread's 8 columns (same layout as a hidden row)
    int col0 = bn + tx * 8;
    float ws[8], wd[8];
    *(float4*)(ws)     = *(const float4*)(att_src + col0);
    *(float4*)(ws + 4) = *(const float4*)(att_src + col0 + 4);
    *(float4*)(wd)     = *(const float4*)(att_dst + col0);
    *(float4*)(wd + 4) = *(const float4*)(att_dst + col0 + 4);
    int head = col0 >> 5;            // 32 channels per head; tx/4 gives head idx

    #pragma unroll
    for (int i = 0; i < 8; i++) {
        int r = bm + ty * 8 + i;
        if (r < NN) {
            float* dst = g_xp + (size_t)r * HID + col0;
            *(float4*)(dst)     = *(float4*)(&acc[i][0]);
            *(float4*)(dst + 4) = *(float4*)(&acc[i][4]);
        }
        // partial head dot products
        float ps = 0.f, pd = 0.f;
        #pragma unroll
        for (int j = 0; j < 8; j++) { ps += acc[i][j] * ws[j]; pd += acc[i][j] * wd[j]; }
        // reduce across the 4 threads (tx%4 group = lane bits 0..1)
        ps += __shfl_xor_sync(0xffffffffu, ps, 1);
        pd += __shfl_xor_sync(0xffffffffu, pd, 1);
        ps += __shfl_xor_sync(0xffffffffu, ps, 2);
        pd += __shfl_xor_sync(0xffffffffu, pd, 2);
        if ((tx & 3) == 0 && r < NN) {
            g_asrc[(size_t)r * HEADS + head] = ps;
            g_adst[(size_t)r * HEADS + head] = pd;
        }
    }
}

// ---------------- edge pass: logits -> leakyrelu -> exp -> CSR slot --------
__global__ __launch_bounds__(256) void edge_ea(const int* __restrict__ ei,
                                               const float* __restrict__ eattr) {
    __shared__ float ws[EDIM * HEADS];
    for (int i = threadIdx.x; i < EDIM * HEADS; i += blockDim.x) ws[i] = g_watt[i];
    __syncthreads();
    int e = blockIdx.x * blockDim.x + threadIdx.x;
    if (e >= EE) return;
    int src = ei[e];
    int dst = ei[EE + e];

    const float4* as4 = (const float4*)(g_asrc + (size_t)src * HEADS);
    const float4* ad4 = (const float4*)(g_adst + (size_t)dst * HEADS);
    float4 as0 = as4[0], as1 = as4[1];
    float4 ad0 = ad4[0], ad1 = ad4[1];

    float acc[HEADS];
    #pragma unroll
    for (int h = 0; h < HEADS; h++) acc[h] = 0.f;

    const float4* ea4 = (const float4*)(eattr + (size_t)e * EDIM);
    #pragma unroll
    for (int d4 = 0; d4 < EDIM / 4; d4++) {
        float4 v = ea4[d4];
        int d = d4 * 4;
        #pragma unroll
        for (int h = 0; h < HEADS; h++) acc[h] += v.x * ws[(d + 0) * HEADS + h];
        #pragma unroll
        for (int h = 0; h < HEADS; h++) acc[h] += v.y * ws[(d + 1) * HEADS + h];
        #pragma unroll
        for (int h = 0; h < HEADS; h++) acc[h] += v.z * ws[(d + 2) * HEADS + h];
        #pragma unroll
        for (int h = 0; h < HEADS; h++) acc[h] += v.w * ws[(d + 3) * HEADS + h];
    }

    float a[HEADS];
    a[0] = as0.x + ad0.x + acc[0];
    a[1] = as0.y + ad0.y + acc[1];
    a[2] = as0.z + ad0.z + acc[2];
    a[3] = as0.w + ad0.w + acc[3];
    a[4] = as1.x + ad1.x + acc[4];
    a[5] = as1.y + ad1.y + acc[5];
    a[6] = as1.z + ad1.z + acc[6];
    a[7] = as1.w + ad1.w + acc[7];

    #pragma unroll
    for (int h = 0; h < HEADS; h++) {
        float al = a[h];
        al = (al > 0.f) ? al : 0.2f * al;   // LeakyReLU
        a[h] = __expf(al);                  // softmax is shift-invariant
    }
    int pos = g_pos[e];
    float4* out = (float4*)(g_ea + (size_t)pos * HEADS);
    out[0] = make_float4(a[0], a[1], a[2], a[3]);
    out[1] = make_float4(a[4], a[5], a[6], a[7]);
}

// ---------------- aggregate (gather) + residual + LayerNorm ----------------
__global__ __launch_bounds__(256) void aggregate(const float* __restrict__ x,
                                                 const float* __restrict__ bias,
                                                 const float* __restrict__ gamma,
                                                 const float* __restrict__ beta,
                                                 float* __restrict__ out) {
    int n = (blockIdx.x * blockDim.x + threadIdx.x) >> 5;
    int lane = threadIdx.x & 31;
    if (n >= NN) return;
    int start = g_start[n];
    int deg   = g_deg[n];
    int ha = lane >> 3;        // head for channels lane*4..
    int hb = 4 + (lane >> 3);

    float4 acc_a = make_float4(0.f, 0.f, 0.f, 0.f);
    float4 acc_b = make_float4(0.f, 0.f, 0.f, 0.f);
    float den = 0.f;

    int i = 0;
    for (; i + 2 <= deg; i += 2) {
        int p0 = start + i, p1 = p0 + 1;
        int s0 = g_csr_src[p0];
        int s1 = g_csr_src[p1];
        float e0 = 0.f, e1 = 0.f;
        if (lane < 8) {
            e0 = g_ea[(size_t)p0 * HEADS + lane];
            e1 = g_ea[(size_t)p1 * HEADS + lane];
        }
        const float4* q0 = (const float4*)g_xp + (size_t)s0 * (HID / 4);
        const float4* q1 = (const float4*)g_xp + (size_t)s1 * (HID / 4);
        float4 g0a = q0[lane], g0b = q0[32 + lane];
        float4 g1a = q1[lane], g1b = q1[32 + lane];
        den += e0 + e1;
        float e0a = __shfl_sync(0xffffffffu, e0, ha);
        float e0b = __shfl_sync(0xffffffffu, e0, hb);
        float e1a = __shfl_sync(0xffffffffu, e1, ha);
        float e1b = __shfl_sync(0xffffffffu, e1, hb);
        acc_a.x += e0a * g0a.x + e1a * g1a.x;
        acc_a.y += e0a * g0a.y + e1a * g1a.y;
        acc_a.z += e0a * g0a.z + e1a * g1a.z;
        acc_a.w += e0a * g0a.w + e1a * g1a.w;
        acc_b.x += e0b * g0b.x + e1b * g1b.x;
        acc_b.y += e0b * g0b.y + e1b * g1b.y;
        acc_b.z += e0b * g0b.z + e1b * g1b.z;
        acc_b.w += e0b * g0b.w + e1b * g1b.w;
    }
    if (i < deg) {
        int p = start + i;
        int src = g_csr_src[p];
        float eav = 0.f;
        if (lane < 8) eav = g_ea[(size_t)p * HEADS + lane];
        den += eav;
        float ea_a = __shfl_sync(0xffffffffu, eav, ha);
        float ea_b = __shfl_sync(0xffffffffu, eav, hb);
        const float4* xp4 = (const float4*)g_xp + (size_t)src * (HID / 4);
        float4 g0 = xp4[lane];
        float4 g1 = xp4[32 + lane];
        acc_a.x += ea_a * g0.x; acc_a.y += ea_a * g0.y;
        acc_a.z += ea_a * g0.z; acc_a.w += ea_a * g0.w;
        acc_b.x += ea_b * g1.x; acc_b.y += ea_b * g1.y;
        acc_b.z += ea_b * g1.z; acc_b.w += ea_b * g1.w;
    }

    float inv = 1.f / (den + 1e-16f);    // lanes 0..7 hold per-head den
    float inv_a = __shfl_sync(0xffffffffu, inv, ha);
    float inv_b = __shfl_sync(0xffffffffu, inv, hb);

    const float4* x4 = (const float4*)x + (size_t)n * (HID / 4);
    float4 xa = x4[lane], xb = x4[32 + lane];
    float4 ba = ((const float4*)bias)[lane];
    float4 bb = ((const float4*)bias)[32 + lane];

    float4 va, vb;
    va.x = xa.x + acc_a.x * inv_a + ba.x;
    va.y = xa.y + acc_a.y * inv_a + ba.y;
    va.z = xa.z + acc_a.z * inv_a + ba.z;
    va.w = xa.w + acc_a.w * inv_a + ba.w;
    vb.x = xb.x + acc_b.x * inv_b + bb.x;
    vb.y = xb.y + acc_b.y * inv_b + bb.y;
    vb.z = xb.z + acc_b.z * inv_b + bb.z;
    vb.w = xb.w + acc_b.w * inv_b + bb.w;

    float s = va.x + va.y + va.z + va.w + vb.x + vb.y + vb.z + vb.w;
    float q = va.x * va.x + va.y * va.y + va.z * va.z + va.w * va.w
            + vb.x * vb.x + vb.y * vb.y + vb.z * vb.z + vb.w * vb.w;
    #pragma unroll
    for (int o = 16; o > 0; o >>= 1) {
        s += __shfl_xor_sync(0xffffffffu, s, o);
        q += __shfl_xor_sync(0xffffffffu, q, o);
    }
    float mu = s * (1.f / HID);
    float var = q * (1.f / HID) - mu * mu;
    float rstd = rsqrtf(var + 1e-5f);

    float4 ga = ((const float4*)gamma)[lane];
    float4 gb = ((const float4*)gamma)[32 + lane];
    float4 be = ((const float4*)beta)[lane];
    float4 bf = ((const float4*)beta)[32 + lane];

    float4 oa, ob;
    oa.x = (va.x - mu) * rstd * ga.x + be.x;
    oa.y = (va.y - mu) * rstd * ga.y + be.y;
    oa.z = (va.z - mu) * rstd * ga.z + be.z;
    oa.w = (va.w - mu) * rstd * ga.w + be.w;
    ob.x = (vb.x - mu) * rstd * gb.x + bf.x;
    ob.y = (vb.y - mu) * rstd * gb.y + bf.y;
    ob.z = (vb.z - mu) * rstd * gb.z + bf.z;
    ob.w = (vb.w - mu) * rstd * gb.w + bf.w;

    float4* o4 = (float4*)out + (size_t)n * (HID / 4);
    o4[lane] = oa;
    o4[32 + lane] = ob;
}

// ---------------- launch ----------------
extern "C" void kernel_launch(void* const* d_in, const int* in_sizes, int n_in,
                              void* d_out, int out_size) {
    const float* x        = (const float*)d_in[0];
    const int*   ei       = (const int*)  d_in[1];
    const float* eattr    = (const float*)d_in[2];
    const float* W        = (const float*)d_in[3];
    const float* W_e      = (const float*)d_in[4];
    const float* att_src  = (const float*)d_in[5];
    const float* att_dst  = (const float*)d_in[6];
    const float* att_edge = (const float*)d_in[7];
    const float* bias     = (const float*)d_in[8];
    const float* gamma    = (const float*)d_in[9];
    const float* beta     = (const float*)d_in[10];
    float* out = (float*)d_out;

    zero_deg<<<(NN + 255) / 256, 256>>>();
    compute_watt<<<1, EDIM * HEADS>>>(W_e, att_edge);
    count_deg<<<(EE + 255) / 256, 256>>>(ei);
    reserve_csr<<<(NN + 255) / 256, 256>>>();
    scatter_csr<<<(EE + 255) / 256, 256>>>(ei);

    dim3 ggrid(HID / GN, (NN + GM - 1) / GM);
    sgemm_xW<<<ggrid, 256>>>(x, W, att_src, att_dst);

    edge_ea<<<(EE + 255) / 256, 256>>>(ei, eattr);
    aggregate<<<(NN * 32 + 255) / 256, 256>>>(x, bias, gamma, beta, out);
}

// round 5
// speedup vs baseline: 1.4619x; 1.0143x over previous
#include <cuda_runtime.h>
#include <cstdint>

#define NN 50000
#define EE 800000
#define HID 256
#define HEADS 8
#define CPH 32
#define EDIM 64

// ---------------- scratch ----------------
__device__ float g_xp  [(size_t)NN * HID];   // x @ W
__device__ float g_ea  [(size_t)EE * HEADS]; // exp(leakyrelu(logit)), CSR order
__device__ float g_asrc[(size_t)NN * HEADS];
__device__ float g_adst[(size_t)NN * HEADS];
__device__ float g_watt[EDIM * HEADS];
__device__ int   g_deg [NN];
__device__ int   g_start[NN];
__device__ int   g_cur [NN];
__device__ int   g_csr_src[EE];
__device__ int   g_total;

// ---------------- zero counters ----------------
__global__ void zero_deg() {
    int i = blockIdx.x * blockDim.x + threadIdx.x;
    if (i < NN) g_deg[i] = 0;
    if (i == 0) g_total = 0;
}

// ---------------- fold W_e with att_edge ----------------
__global__ void compute_watt(const float* __restrict__ W_e,
                             const float* __restrict__ att_edge) {
    int i = threadIdx.x;              // 512 threads
    int d = i >> 3, h = i & 7;
    float s = 0.f;
    #pragma unroll
    for (int c = 0; c < CPH; c++)
        s += W_e[d * (HEADS * CPH) + h * CPH + c] * att_edge[h * CPH + c];
    g_watt[d * HEADS + h] = s;
}

// ---------------- CSR build ----------------
__global__ void count_deg(const int* __restrict__ ei) {
    int e = blockIdx.x * blockDim.x + threadIdx.x;
    if (e < EE) atomicAdd(&g_deg[ei[EE + e]], 1);
}

// warp-scan + atomic region reservation (placement order is irrelevant)
__global__ void reserve_csr() {
    int n = blockIdx.x * blockDim.x + threadIdx.x;
    int lane = threadIdx.x & 31;
    int d = (n < NN) ? g_deg[n] : 0;
    int incl = d;
    #pragma unroll
    for (int o = 1; o < 32; o <<= 1) {
        int v = __shfl_up_sync(0xffffffffu, incl, o);
        if (lane >= o) incl += v;
    }
    int wtotal = __shfl_sync(0xffffffffu, incl, 31);
    int base = 0;
    if (lane == 31) base = atomicAdd(&g_total, wtotal);
    base = __shfl_sync(0xffffffffu, base, 31);
    int start = base + incl - d;
    if (n < NN) { g_start[n] = start; g_cur[n] = start; }
}

// ---------------- xp = x @ W : 128x128x16 SGEMM + prefetch + att epilogue --
#define GM 128
#define GN 128
#define GK 16
__global__ __launch_bounds__(256, 2) void sgemm_xW(const float* __restrict__ A,
                                                   const float* __restrict__ B,
                                                   const float* __restrict__ att_src,
                                                   const float* __restrict__ att_dst) {
    __shared__ float As[GK][GM + 4];   // +4 pad keeps rows 16B-aligned for LDS.128
    __shared__ float Bs[GK][GN];
    int bm = blockIdx.y * GM;
    int bn = blockIdx.x * GN;
    int t = threadIdx.x;
    int tx = t & 15;       // col block  tx*8
    int ty = t >> 4;       // row block  ty*8
    int arow = t >> 1, aseg = (t & 1) * 8;
    int brow = t >> 4, bcol = (t & 15) * 8;

    const float* aptr = A + (size_t)(bm + arow) * HID + aseg;
    const float* bptr = B + (size_t)brow * HID + bn + bcol;
    bool arow_ok = (bm + arow) < NN;

    float4 pa0, pa1, pb0, pb1;
    pa0 = make_float4(0.f, 0.f, 0.f, 0.f); pa1 = pa0;
    if (arow_ok) { pa0 = *(const float4*)(aptr); pa1 = *(const float4*)(aptr + 4); }
    pb0 = *(const float4*)(bptr);
    pb1 = *(const float4*)(bptr + 4);

    float acc[8][8];
    #pragma unroll
    for (int i = 0; i < 8; i++)
        #pragma unroll
        for (int j = 0; j < 8; j++) acc[i][j] = 0.f;

    #pragma unroll 1
    for (int kt = 0; kt < HID / GK; kt++) {
        As[aseg + 0][arow] = pa0.x;
        As[aseg + 1][arow] = pa0.y;
        As[aseg + 2][arow] = pa0.z;
        As[aseg + 3][arow] = pa0.w;
        As[aseg + 4][arow] = pa1.x;
        As[aseg + 5][arow] = pa1.y;
        As[aseg + 6][arow] = pa1.z;
        As[aseg + 7][arow] = pa1.w;
        *(float4*)(&Bs[brow][bcol])     = pb0;
        *(float4*)(&Bs[brow][bcol + 4]) = pb1;
        __syncthreads();
        if (kt + 1 < HID / GK) {
            const float* ap = aptr + (kt + 1) * GK;
            const float* bp = bptr + (size_t)(kt + 1) * GK * HID;
            if (arow_ok) { pa0 = *(const float4*)(ap); pa1 = *(const float4*)(ap + 4); }
            pb0 = *(const float4*)(bp);
            pb1 = *(const float4*)(bp + 4);
        }
        #pragma unroll
        for (int k = 0; k < GK; k++) {
            float a[8], b[8];
            *(float4*)(a)     = *(float4*)(&As[k][ty * 8]);
            *(float4*)(a + 4) = *(float4*)(&As[k][ty * 8 + 4]);
            *(float4*)(b)     = *(float4*)(&Bs[k][tx * 8]);
            *(float4*)(b + 4) = *(float4*)(&Bs[k][tx * 8 + 4]);
            #pragma unroll
            for (int i = 0; i < 8; i++)
                #pragma unroll
                for (int j = 0; j < 8; j++) acc[i][j] += a[i] * b[j];
        }
        __syncthreads();
    }

    // fused node_att epilogue: this thread's 8 cols lie in one head (32ch/head)
    int col0 = bn + tx * 8;
    float ws[8], wd[8];
    *(float4*)(ws)     = *(const float4*)(att_src + col0);
    *(float4*)(ws + 4) = *(const float4*)(att_src + col0 + 4);
    *(float4*)(wd)     = *(const float4*)(att_dst + col0);
    *(float4*)(wd + 4) = *(const float4*)(att_dst + col0 + 4);
    int head = col0 >> 5;

    #pragma unroll
    for (int i = 0; i < 8; i++) {
        int r = bm + ty * 8 + i;
        if (r < NN) {
            float* dst = g_xp + (size_t)r * HID + col0;
            *(float4*)(dst)     = *(float4*)(&acc[i][0]);
            *(float4*)(dst + 4) = *(float4*)(&acc[i][4]);
        }
        float ps = 0.f, pd = 0.f;
        #pragma unroll
        for (int j = 0; j < 8; j++) { ps += acc[i][j] * ws[j]; pd += acc[i][j] * wd[j]; }
        ps += __shfl_xor_sync(0xffffffffu, ps, 1);
        pd += __shfl_xor_sync(0xffffffffu, pd, 1);
        ps += __shfl_xor_sync(0xffffffffu, ps, 2);
        pd += __shfl_xor_sync(0xffffffffu, pd, 2);
        if ((tx & 3) == 0 && r < NN) {
            g_asrc[(size_t)r * HEADS + head] = ps;
            g_adst[(size_t)r * HEADS + head] = pd;
        }
    }
}

// -------- edge pass: logits -> leakyrelu -> exp + fused CSR scatter --------
__global__ __launch_bounds__(256) void edge_ea(const int* __restrict__ ei,
                                               const float* __restrict__ eattr) {
    __shared__ float ws[EDIM * HEADS];
    for (int i = threadIdx.x; i < EDIM * HEADS; i += blockDim.x) ws[i] = g_watt[i];
    __syncthreads();
    int e = blockIdx.x * blockDim.x + threadIdx.x;
    if (e >= EE) return;
    int src = ei[e];
    int dst = ei[EE + e];

    const float4* as4 = (const float4*)(g_asrc + (size_t)src * HEADS);
    const float4* ad4 = (const float4*)(g_adst + (size_t)dst * HEADS);
    float4 as0 = as4[0], as1 = as4[1];
    float4 ad0 = ad4[0], ad1 = ad4[1];

    float acc[HEADS];
    #pragma unroll
    for (int h = 0; h < HEADS; h++) acc[h] = 0.f;

    const float4* ea4 = (const float4*)(eattr + (size_t)e * EDIM);
    #pragma unroll
    for (int d4 = 0; d4 < EDIM / 4; d4++) {
        float4 v = ea4[d4];
        int d = d4 * 4;
        #pragma unroll
        for (int h = 0; h < HEADS; h++) acc[h] += v.x * ws[(d + 0) * HEADS + h];
        #pragma unroll
        for (int h = 0; h < HEADS; h++) acc[h] += v.y * ws[(d + 1) * HEADS + h];
        #pragma unroll
        for (int h = 0; h < HEADS; h++) acc[h] += v.z * ws[(d + 2) * HEADS + h];
        #pragma unroll
        for (int h = 0; h < HEADS; h++) acc[h] += v.w * ws[(d + 3) * HEADS + h];
    }

    float a[HEADS];
    a[0] = as0.x + ad0.x + acc[0];
    a[1] = as0.y + ad0.y + acc[1];
    a[2] = as0.z + ad0.z + acc[2];
    a[3] = as0.w + ad0.w + acc[3];
    a[4] = as1.x + ad1.x + acc[4];
    a[5] = as1.y + ad1.y + acc[5];
    a[6] = as1.z + ad1.z + acc[6];
    a[7] = as1.w + ad1.w + acc[7];

    #pragma unroll
    for (int h = 0; h < HEADS; h++) {
        float al = a[h];
        al = (al > 0.f) ? al : 0.2f * al;   // LeakyReLU
        a[h] = __expf(al);                  // softmax is shift-invariant
    }
    int pos = atomicAdd(&g_cur[dst], 1);    // fused CSR slot reservation
    g_csr_src[pos] = src;
    float4* out = (float4*)(g_ea + (size_t)pos * HEADS);
    out[0] = make_float4(a[0], a[1], a[2], a[3]);
    out[1] = make_float4(a[4], a[5], a[6], a[7]);
}

// -------- aggregate: 2 warps/node, batched index loads, residual + LN ------
__global__ __launch_bounds__(256) void aggregate(const float* __restrict__ x,
                                                 const float* __restrict__ bias,
                                                 const float* __restrict__ gamma,
                                                 const float* __restrict__ beta,
                                                 float* __restrict__ out) {
    __shared__ float s2[8], q2[8];
    int warp = threadIdx.x >> 5;             // 0..7
    int node = blockIdx.x * 4 + (warp >> 1);
    int half = warp & 1;                     // channel half: half*128 ..
    int lane = threadIdx.x & 31;
    bool valid = node < NN;
    int start = valid ? g_start[node] : 0;
    int deg   = valid ? g_deg[node] : 0;

    // my 4 channels: c0 = half*128 + lane*4; head = half*4 + (lane>>3)
    float4 acc = make_float4(0.f, 0.f, 0.f, 0.f);
    float den_part = 0.f;   // lane holds (edge slot lane>>2, head half*4+(lane&3))

    int i0 = 0;
    for (; i0 + 8 <= deg; i0 += 8) {
        int p0 = start + i0;
        int srcs = (lane < 8) ? g_csr_src[p0 + lane] : 0;
        float eav = g_ea[(size_t)(p0 + (lane >> 2)) * HEADS + half * 4 + (lane & 3)];
        den_part += eav;
        #pragma unroll
        for (int j = 0; j < 8; j++) {
            int src = __shfl_sync(0xffffffffu, srcs, j);
            float eh = __shfl_sync(0xffffffffu, eav, j * 4 + (lane >> 3));
            const float4* q = (const float4*)g_xp + (size_t)src * (HID / 4) + half * 32;
            float4 g = q[lane];
            acc.x += eh * g.x; acc.y += eh * g.y;
            acc.z += eh * g.z; acc.w += eh * g.w;
        }
    }
    if (i0 < deg) {
        int rem = deg - i0;
        int p0 = start + i0;
        int srcs = (lane < 8 && lane < rem) ? g_csr_src[p0 + lane] : 0;
        float eav = ((lane >> 2) < rem)
                  ? g_ea[(size_t)(p0 + (lane >> 2)) * HEADS + half * 4 + (lane & 3)]
                  : 0.f;
        den_part += eav;
        for (int j = 0; j < rem; j++) {
            int src = __shfl_sync(0xffffffffu, srcs, j);
            float eh = __shfl_sync(0xffffffffu, eav, j * 4 + (lane >> 3));
            const float4* q = (const float4*)g_xp + (size_t)src * (HID / 4) + half * 32;
            float4 g = q[lane];
            acc.x += eh * g.x; acc.y += eh * g.y;
            acc.z += eh * g.z; acc.w += eh * g.w;
        }
    }

    // reduce den over edge-slot lanes (bits 2..4); head = lane&3 everywhere after
    #pragma unroll
    for (int o = 4; o < 32; o <<= 1)
        den_part += __shfl_xor_sync(0xffffffffu, den_part, o);
    float inv = 1.f / (den_part + 1e-16f);          // lane l: head l&3
    float inv_t = __shfl_sync(0xffffffffu, inv, lane >> 3);  // my head

    int c4 = half * 32 + lane;   // float4 index of my channels
    size_t xidx = valid ? ((size_t)node * (HID / 4) + c4) : 0;
    float4 xa = ((const float4*)x)[xidx];
    float4 ba = ((const float4*)bias)[c4];

    float4 va;
    va.x = xa.x + acc.x * inv_t + ba.x;
    va.y = xa.y + acc.y * inv_t + ba.y;
    va.z = xa.z + acc.z * inv_t + ba.z;
    va.w = xa.w + acc.w * inv_t + ba.w;

    float s = va.x + va.y + va.z + va.w;
    float q = va.x * va.x + va.y * va.y + va.z * va.z + va.w * va.w;
    #pragma unroll
    for (int o = 16; o > 0; o >>= 1) {
        s += __shfl_xor_sync(0xffffffffu, s, o);
        q += __shfl_xor_sync(0xffffffffu, q, o);
    }
    if (lane == 0) { s2[warp] = s; q2[warp] = q; }
    __syncthreads();
    float ts = s2[warp] + s2[warp ^ 1];
    float tq = q2[warp] + q2[warp ^ 1];
    float mu = ts * (1.f / HID);
    float var = tq * (1.f / HID) - mu * mu;
    float rstd = rsqrtf(var + 1e-5f);

    float4 ga = ((const float4*)gamma)[c4];
    float4 be = ((const float4*)beta)[c4];
    float4 oa;
    oa.x = (va.x - mu) * rstd * ga.x + be.x;
    oa.y = (va.y - mu) * rstd * ga.y + be.y;
    oa.z = (va.z - mu) * rstd * ga.z + be.z;
    oa.w = (va.w - mu) * rstd * ga.w + be.w;

    if (valid)
        ((float4*)out)[(size_t)node * (HID / 4) + c4] = oa;
}

// ---------------- launch ----------------
extern "C" void kernel_launch(void* const* d_in, const int* in_sizes, int n_in,
                              void* d_out, int out_size) {
    const float* x        = (const float*)d_in[0];
    const int*   ei       = (const int*)  d_in[1];
    const float* eattr    = (const float*)d_in[2];
    const float* W        = (const float*)d_in[3];
    const float* W_e      = (const float*)d_in[4];
    const float* att_src  = (const float*)d_in[5];
    const float* att_dst  = (const float*)d_in[6];
    const float* att_edge = (const float*)d_in[7];
    const float* bias     = (const float*)d_in[8];
    const float* gamma    = (const float*)d_in[9];
    const float* beta     = (const float*)d_in[10];
    float* out = (float*)d_out;

    zero_deg<<<(NN + 255) / 256, 256>>>();
    compute_watt<<<1, EDIM * HEADS>>>(W_e, att_edge);
    count_deg<<<(EE + 255) / 256, 256>>>(ei);
    reserve_csr<<<(NN + 255) / 256, 256>>>();

    dim3 ggrid(HID / GN, (NN + GM - 1) / GM);
    sgemm_xW<<<ggrid, 256>>>(x, W, att_src, att_dst);

    edge_ea<<<(EE + 255) / 256, 256>>>(ei, eattr);
    aggregate<<<(NN + 3) / 4, 256>>>(x, bias, gamma, beta, out);
}

// round 8
// speedup vs baseline: 1.7615x; 1.2049x over previous
#include <cuda_runtime.h>
#include <cuda_bf16.h>
#include <cstdint>

#define NN 50000
#define EE 800000
#define HID 256
#define HEADS 8
#define CPH 32
#define EDIM 64

// ---------------- scratch ----------------
__device__ float          g_xp  [(size_t)NN * HID];   // x @ W
__device__ float          g_ea  [(size_t)EE * HEADS]; // exp(leakyrelu(logit)), CSR order
__device__ float          g_asrc[(size_t)NN * HEADS];
__device__ float          g_adst[(size_t)NN * HEADS];
__device__ float          g_watt[EDIM * HEADS];
__device__ int            g_deg [NN];
__device__ int            g_start[NN];
__device__ int            g_cur [NN];
__device__ int            g_csr_src[EE];
__device__ int            g_total;
__device__ __nv_bfloat16  g_xhi[(size_t)NN * HID];
__device__ __nv_bfloat16  g_xlo[(size_t)NN * HID];
__device__ __nv_bfloat16  g_whi[HID * HID];   // [n][k] = W[k][n]
__device__ __nv_bfloat16  g_wlo[HID * HID];

// ---------------- zero counters ----------------
__global__ void zero_deg() {
    int i = blockIdx.x * blockDim.x + threadIdx.x;
    if (i < NN) g_deg[i] = 0;
    if (i == 0) g_total = 0;
}

// ---------------- fold W_e with att_edge ----------------
__global__ void compute_watt(const float* __restrict__ W_e,
                             const float* __restrict__ att_edge) {
    int i = threadIdx.x;              // 512 threads
    int d = i >> 3, h = i & 7;
    float s = 0.f;
    #pragma unroll
    for (int c = 0; c < CPH; c++)
        s += W_e[d * (HEADS * CPH) + h * CPH + c] * att_edge[h * CPH + c];
    g_watt[d * HEADS + h] = s;
}

// ---------------- CSR build ----------------
__global__ void count_deg(const int* __restrict__ ei) {
    int e = blockIdx.x * blockDim.x + threadIdx.x;
    if (e < EE) atomicAdd(&g_deg[ei[EE + e]], 1);
}

__global__ void reserve_csr() {
    int n = blockIdx.x * blockDim.x + threadIdx.x;
    int lane = threadIdx.x & 31;
    int d = (n < NN) ? g_deg[n] : 0;
    int incl = d;
    #pragma unroll
    for (int o = 1; o < 32; o <<= 1) {
        int v = __shfl_up_sync(0xffffffffu, incl, o);
        if (lane >= o) incl += v;
    }
    int wtotal = __shfl_sync(0xffffffffu, incl, 31);
    int base = 0;
    if (lane == 31) base = atomicAdd(&g_total, wtotal);
    base = __shfl_sync(0xffffffffu, base, 31);
    int start = base + incl - d;
    if (n < NN) { g_start[n] = start; g_cur[n] = start; }
}

// ---------------- fp32 -> bf16 hi/lo split ----------------
__global__ void convert_x(const float* __restrict__ x) {
    size_t i = ((size_t)blockIdx.x * blockDim.x + threadIdx.x) * 4;
    if (i >= (size_t)NN * HID) return;
    float4 v = *(const float4*)(x + i);
    __nv_bfloat16 h0 = __float2bfloat16(v.x);
    __nv_bfloat16 h1 = __float2bfloat16(v.y);
    __nv_bfloat16 h2 = __float2bfloat16(v.z);
    __nv_bfloat16 h3 = __float2bfloat16(v.w);
    __nv_bfloat162 hi0; hi0.x = h0; hi0.y = h1;
    __nv_bfloat162 hi1; hi1.x = h2; hi1.y = h3;
    __nv_bfloat162 lo0, lo1;
    lo0.x = __float2bfloat16(v.x - __bfloat162float(h0));
    lo0.y = __float2bfloat16(v.y - __bfloat162float(h1));
    lo1.x = __float2bfloat16(v.z - __bfloat162float(h2));
    lo1.y = __float2bfloat16(v.w - __bfloat162float(h3));
    *(__nv_bfloat162*)(g_xhi + i)     = hi0;
    *(__nv_bfloat162*)(g_xhi + i + 2) = hi1;
    *(__nv_bfloat162*)(g_xlo + i)     = lo0;
    *(__nv_bfloat162*)(g_xlo + i + 2) = lo1;
}

__global__ void convert_w(const float* __restrict__ W) {
    int i = blockIdx.x * blockDim.x + threadIdx.x;  // 65536
    if (i >= HID * HID) return;
    int n = i >> 8, k = i & 255;
    float v = W[k * HID + n];                        // transpose: B[n][k] = W[k][n]
    __nv_bfloat16 hi = __float2bfloat16(v);
    g_whi[i] = hi;
    g_wlo[i] = __float2bfloat16(v - __bfloat162float(hi));
}

// ================ mma.sync bf16 GEMM (compute_103-legal tensor path) =======
__device__ __forceinline__ void ldsm_x4(uint32_t addr, uint32_t& r0, uint32_t& r1,
                                        uint32_t& r2, uint32_t& r3) {
    asm volatile("ldmatrix.sync.aligned.m8n8.x4.shared.b16 {%0,%1,%2,%3}, [%4];"
                 : "=r"(r0), "=r"(r1), "=r"(r2), "=r"(r3) : "r"(addr));
}
__device__ __forceinline__ void mma_bf16(float* c, const uint32_t* a,
                                         uint32_t b0, uint32_t b1) {
    asm volatile(
        "mma.sync.aligned.m16n8k16.row.col.f32.bf16.bf16.f32 "
        "{%0,%1,%2,%3}, {%4,%5,%6,%7}, {%8,%9}, {%0,%1,%2,%3};"
        : "+f"(c[0]), "+f"(c[1]), "+f"(c[2]), "+f"(c[3])
        : "r"(a[0]), "r"(a[1]), "r"(a[2]), "r"(a[3]), "r"(b0), "r"(b1));
}
__device__ __forceinline__ uint32_t smem_u32(const void* p) {
    uint32_t a;
    asm("{ .reg .u64 t; cvta.to.shared.u64 t, %1; cvt.u32.u64 %0, t; }"
        : "=r"(a) : "l"(p));
    return a;
}

// SMEM layout (dynamic): swizzled tiles, 128B rows of 8x16B chunks
#define SM_AHI  0
#define SM_ALO  16384
#define SM_BHI  32768
#define SM_BLO  40960
#define SM_ATTS 49152
#define SM_ATTD 49408
#define SM_SZ   49664
#define SWO(row, c) ((uint32_t)((row) * 128 + (((c) ^ ((row) & 7)) << 4)))

__global__ __launch_bounds__(256, 2) void gemm_mma(const float* __restrict__ att_src,
                                                   const float* __restrict__ att_dst) {
    extern __shared__ char smem[];
    uint32_t sb = smem_u32(smem);
    int tid = threadIdx.x;
    int wid = tid >> 5;
    int lane = tid & 31;
    int bm = blockIdx.y * 128;
    int bn = blockIdx.x * 64;
    int mrow0 = (wid & 3) * 32;
    int ncol0 = (wid >> 2) * 32;

    float* satts = (float*)(smem + SM_ATTS);
    float* sattd = (float*)(smem + SM_ATTD);
    if (tid < 64) {
        satts[tid] = att_src[bn + tid];
        sattd[tid] = att_dst[bn + tid];
    }

    float acc[2][4][4];
    #pragma unroll
    for (int ma = 0; ma < 2; ma++)
        #pragma unroll
        for (int nb = 0; nb < 4; nb++)
            #pragma unroll
            for (int j = 0; j < 4; j++) acc[ma][nb][j] = 0.f;

    // precomputed fragment smem addresses (depend only on lane/warp/ks)
    #pragma unroll 1
    for (int kc = 0; kc < 4; kc++) {
        // ---- stage A (128x64, hi+lo) ----
        #pragma unroll
        for (int j = 0; j < 4; j++) {
            int i = tid + j * 256;
            int row = i >> 3, c = i & 7;
            uint32_t off = SWO(row, c);
            int rg = bm + row;
            uint4 vh = make_uint4(0, 0, 0, 0), vl = make_uint4(0, 0, 0, 0);
            if (rg < NN) {
                const __nv_bfloat16* ph = g_xhi + ((size_t)rg << 8) + kc * 64 + c * 8;
                const __nv_bfloat16* pl = g_xlo + ((size_t)rg << 8) + kc * 64 + c * 8;
                vh = *(const uint4*)ph;
                vl = *(const uint4*)pl;
            }
            *(uint4*)(smem + SM_AHI + off) = vh;
            *(uint4*)(smem + SM_ALO + off) = vl;
        }
        // ---- stage B (64x64, hi+lo), rows are n, cols are k ----
        #pragma unroll
        for (int j = 0; j < 2; j++) {
            int i = tid + j * 256;
            int n = i >> 3, c = i & 7;
            uint32_t off = SWO(n, c);
            const __nv_bfloat16* ph = g_whi + ((size_t)(bn + n) << 8) + kc * 64 + c * 8;
            const __nv_bfloat16* pl = g_wlo + ((size_t)(bn + n) << 8) + kc * 64 + c * 8;
            *(uint4*)(smem + SM_BHI + off) = *(const uint4*)ph;
            *(uint4*)(smem + SM_BLO + off) = *(const uint4*)pl;
        }
        __syncthreads();

        #pragma unroll
        for (int ks = 0; ks < 4; ks++) {
            // A fragments: row = mrow0 + ma*16 + (lane&15), chunk = ks*2 + (lane>>4)
            uint32_t ahi[2][4], alo[2][4];
            #pragma unroll
            for (int ma = 0; ma < 2; ma++) {
                int row = mrow0 + ma * 16 + (lane & 15);
                int c = ks * 2 + (lane >> 4);
                uint32_t off = SWO(row, c);
                ldsm_x4(sb + SM_AHI + off, ahi[ma][0], ahi[ma][1], ahi[ma][2], ahi[ma][3]);
                ldsm_x4(sb + SM_ALO + off, alo[ma][0], alo[ma][1], alo[ma][2], alo[ma][3]);
            }
            // B fragments: 2 x4 loads cover 4 n-blocks of 8
            uint32_t bhi[4][2], blo[4][2];
            #pragma unroll
            for (int nb2 = 0; nb2 < 2; nb2++) {
                int n = ncol0 + nb2 * 16 + (lane & 7) + ((lane & 16) >> 1);
                int c = ks * 2 + ((lane >> 3) & 1);
                uint32_t off = SWO(n, c);
                ldsm_x4(sb + SM_BHI + off, bhi[nb2 * 2][0], bhi[nb2 * 2][1],
                        bhi[nb2 * 2 + 1][0], bhi[nb2 * 2 + 1][1]);
                ldsm_x4(sb + SM_BLO + off, blo[nb2 * 2][0], blo[nb2 * 2][1],
                        blo[nb2 * 2 + 1][0], blo[nb2 * 2 + 1][1]);
            }
            #pragma unroll
            for (int ma = 0; ma < 2; ma++)
                #pragma unroll
                for (int nb = 0; nb < 4; nb++) {
                    mma_bf16(acc[ma][nb], ahi[ma], bhi[nb][0], bhi[nb][1]);
                    mma_bf16(acc[ma][nb], ahi[ma], blo[nb][0], blo[nb][1]);
                    mma_bf16(acc[ma][nb], alo[ma], bhi[nb][0], bhi[nb][1]);
                }
        }
        __syncthreads();
    }

    // ---- epilogue: store xp + fused a_src/a_dst (one head per warp) ----
    int head = (bn + ncol0) >> 5;
    #pragma unroll
    for (int ma = 0; ma < 2; ma++) {
        int row0 = bm + mrow0 + ma * 16 + (lane >> 2);
        int row1 = row0 + 8;
        float ps0 = 0.f, pd0 = 0.f, ps1 = 0.f, pd1 = 0.f;
        #pragma unroll
        for (int nb = 0; nb < 4; nb++) {
            int colt = ncol0 + nb * 8 + (lane & 3) * 2;   // col within 64-tile
            float c0 = acc[ma][nb][0], c1 = acc[ma][nb][1];
            float c2 = acc[ma][nb][2], c3 = acc[ma][nb][3];
            if (row0 < NN)
                *(float2*)(g_xp + (size_t)row0 * HID + bn + colt) = make_float2(c0, c1);
            if (row1 < NN)
                *(float2*)(g_xp + (size_t)row1 * HID + bn + colt) = make_float2(c2, c3);
            float as0 = satts[colt], as1 = satts[colt + 1];
            float ad0 = sattd[colt], ad1 = sattd[colt + 1];
            ps0 += c0 * as0 + c1 * as1;
            pd0 += c0 * ad0 + c1 * ad1;
            ps1 += c2 * as0 + c3 * as1;
            pd1 += c2 * ad0 + c3 * ad1;
        }
        #pragma unroll
        for (int o = 1; o <= 2; o <<= 1) {
            ps0 += __shfl_xor_sync(0xffffffffu, ps0, o);
            pd0 += __shfl_xor_sync(0xffffffffu, pd0, o);
            ps1 += __shfl_xor_sync(0xffffffffu, ps1, o);
            pd1 += __shfl_xor_sync(0xffffffffu, pd1, o);
        }
        if ((lane & 3) == 0) {
            if (row0 < NN) {
                g_asrc[(size_t)row0 * HEADS + head] = ps0;
                g_adst[(size_t)row0 * HEADS + head] = pd0;
            }
            if (row1 < NN) {
                g_asrc[(size_t)row1 * HEADS + head] = ps1;
                g_adst[(size_t)row1 * HEADS + head] = pd1;
            }
        }
    }
}

// -------- edge pass: logits -> leakyrelu -> exp + fused CSR scatter --------
__global__ __launch_bounds__(256) void edge_ea(const int* __restrict__ ei,
                                               const float* __restrict__ eattr) {
    __shared__ float ws[EDIM * HEADS];
    for (int i = threadIdx.x; i < EDIM * HEADS; i += blockDim.x) ws[i] = g_watt[i];
    __syncthreads();
    int e = blockIdx.x * blockDim.x + threadIdx.x;
    if (e >= EE) return;
    int src = ei[e];
    int dst = ei[EE + e];

    const float4* as4 = (const float4*)(g_asrc + (size_t)src * HEADS);
    const float4* ad4 = (const float4*)(g_adst + (size_t)dst * HEADS);
    float4 as0 = as4[0], as1 = as4[1];
    float4 ad0 = ad4[0], ad1 = ad4[1];

    float acc[HEADS];
    #pragma unroll
    for (int h = 0; h < HEADS; h++) acc[h] = 0.f;

    const float4* ea4 = (const float4*)(eattr + (size_t)e * EDIM);
    #pragma unroll
    for (int d4 = 0; d4 < EDIM / 4; d4++) {
        float4 v = ea4[d4];
        int d = d4 * 4;
        #pragma unroll
        for (int h = 0; h < HEADS; h++) acc[h] += v.x * ws[(d + 0) * HEADS + h];
        #pragma unroll
        for (int h = 0; h < HEADS; h++) acc[h] += v.y * ws[(d + 1) * HEADS + h];
        #pragma unroll
        for (int h = 0; h < HEADS; h++) acc[h] += v.z * ws[(d + 2) * HEADS + h];
        #pragma unroll
        for (int h = 0; h < HEADS; h++) acc[h] += v.w * ws[(d + 3) * HEADS + h];
    }

    float a[HEADS];
    a[0] = as0.x + ad0.x + acc[0];
    a[1] = as0.y + ad0.y + acc[1];
    a[2] = as0.z + ad0.z + acc[2];
    a[3] = as0.w + ad0.w + acc[3];
    a[4] = as1.x + ad1.x + acc[4];
    a[5] = as1.y + ad1.y + acc[5];
    a[6] = as1.z + ad1.z + acc[6];
    a[7] = as1.w + ad1.w + acc[7];

    #pragma unroll
    for (int h = 0; h < HEADS; h++) {
        float al = a[h];
        al = (al > 0.f) ? al : 0.2f * al;   // LeakyReLU
        a[h] = __expf(al);                  // softmax is shift-invariant
    }
    int pos = atomicAdd(&g_cur[dst], 1);    // fused CSR slot reservation
    g_csr_src[pos] = src;
    float4* out = (float4*)(g_ea + (size_t)pos * HEADS);
    out[0] = make_float4(a[0], a[1], a[2], a[3]);
    out[1] = make_float4(a[4], a[5], a[6], a[7]);
}

// -------- aggregate: 2 warps/node, batched index loads, residual + LN ------
__global__ __launch_bounds__(256) void aggregate(const float* __restrict__ x,
                                                 const float* __restrict__ bias,
                                                 const float* __restrict__ gamma,
                                                 const float* __restrict__ beta,
                                                 float* __restrict__ out) {
    __shared__ float s2[8], q2[8];
    int warp = threadIdx.x >> 5;             // 0..7
    int node = blockIdx.x * 4 + (warp >> 1);
    int half = warp & 1;                     // channel half: half*128 ..
    int lane = threadIdx.x & 31;
    bool valid = node < NN;
    int start = valid ? g_start[node] : 0;
    int deg   = valid ? g_deg[node] : 0;

    float4 acc = make_float4(0.f, 0.f, 0.f, 0.f);
    float den_part = 0.f;

    int i0 = 0;
    for (; i0 + 8 <= deg; i0 += 8) {
        int p0 = start + i0;
        int srcs = (lane < 8) ? g_csr_src[p0 + lane] : 0;
        float eav = g_ea[(size_t)(p0 + (lane >> 2)) * HEADS + half * 4 + (lane & 3)];
        den_part += eav;
        #pragma unroll
        for (int j = 0; j < 8; j++) {
            int src = __shfl_sync(0xffffffffu, srcs, j);
            float eh = __shfl_sync(0xffffffffu, eav, j * 4 + (lane >> 3));
            const float4* q = (const float4*)g_xp + (size_t)src * (HID / 4) + half * 32;
            float4 g = q[lane];
            acc.x += eh * g.x; acc.y += eh * g.y;
            acc.z += eh * g.z; acc.w += eh * g.w;
        }
    }
    if (i0 < deg) {
        int rem = deg - i0;
        int p0 = start + i0;
        int srcs = (lane < 8 && lane < rem) ? g_csr_src[p0 + lane] : 0;
        float eav = ((lane >> 2) < rem)
                  ? g_ea[(size_t)(p0 + (lane >> 2)) * HEADS + half * 4 + (lane & 3)]
                  : 0.f;
        den_part += eav;
        for (int j = 0; j < rem; j++) {
            int src = __shfl_sync(0xffffffffu, srcs, j);
            float eh = __shfl_sync(0xffffffffu, eav, j * 4 + (lane >> 3));
            const float4* q = (const float4*)g_xp + (size_t)src * (HID / 4) + half * 32;
            float4 g = q[lane];
            acc.x += eh * g.x; acc.y += eh * g.y;
            acc.z += eh * g.z; acc.w += eh * g.w;
        }
    }

    #pragma unroll
    for (int o = 4; o < 32; o <<= 1)
        den_part += __shfl_xor_sync(0xffffffffu, den_part, o);
    float inv = 1.f / (den_part + 1e-16f);
    float inv_t = __shfl_sync(0xffffffffu, inv, lane >> 3);

    int c4 = half * 32 + lane;
    size_t xidx = valid ? ((size_t)node * (HID / 4) + c4) : 0;
    float4 xa = ((const float4*)x)[xidx];
    float4 ba = ((const float4*)bias)[c4];

    float4 va;
    va.x = xa.x + acc.x * inv_t + ba.x;
    va.y = xa.y + acc.y * inv_t + ba.y;
    va.z = xa.z + acc.z * inv_t + ba.z;
    va.w = xa.w + acc.w * inv_t + ba.w;

    float s = va.x + va.y + va.z + va.w;
    float q = va.x * va.x + va.y * va.y + va.z * va.z + va.w * va.w;
    #pragma unroll
    for (int o = 16; o > 0; o >>= 1) {
        s += __shfl_xor_sync(0xffffffffu, s, o);
        q += __shfl_xor_sync(0xffffffffu, q, o);
    }
    if (lane == 0) { s2[warp] = s; q2[warp] = q; }
    __syncthreads();
    float ts = s2[warp] + s2[warp ^ 1];
    float tq = q2[warp] + q2[warp ^ 1];
    float mu = ts * (1.f / HID);
    float var = tq * (1.f / HID) - mu * mu;
    float rstd = rsqrtf(var + 1e-5f);

    float4 ga = ((const float4*)gamma)[c4];
    float4 be = ((const float4*)beta)[c4];
    float4 oa;
    oa.x = (va.x - mu) * rstd * ga.x + be.x;
    oa.y = (va.y - mu) * rstd * ga.y + be.y;
    oa.z = (va.z - mu) * rstd * ga.z + be.z;
    oa.w = (va.w - mu) * rstd * ga.w + be.w;

    if (valid)
        ((float4*)out)[(size_t)node * (HID / 4) + c4] = oa;
}

// ---------------- launch ----------------
extern "C" void kernel_launch(void* const* d_in, const int* in_sizes, int n_in,
                              void* d_out, int out_size) {
    const float* x        = (const float*)d_in[0];
    const int*   ei       = (const int*)  d_in[1];
    const float* eattr    = (const float*)d_in[2];
    const float* W        = (const float*)d_in[3];
    const float* W_e      = (const float*)d_in[4];
    const float* att_src  = (const float*)d_in[5];
    const float* att_dst  = (const float*)d_in[6];
    const float* att_edge = (const float*)d_in[7];
    const float* bias     = (const float*)d_in[8];
    const float* gamma    = (const float*)d_in[9];
    const float* beta     = (const float*)d_in[10];
    float* out = (float*)d_out;

    cudaFuncSetAttribute(gemm_mma, cudaFuncAttributeMaxDynamicSharedMemorySize, SM_SZ);

    zero_deg<<<(NN + 255) / 256, 256>>>();
    compute_watt<<<1, EDIM * HEADS>>>(W_e, att_edge);
    count_deg<<<(EE + 255) / 256, 256>>>(ei);
    reserve_csr<<<(NN + 255) / 256, 256>>>();

    convert_x<<<(NN * HID / 4 + 255) / 256, 256>>>(x);
    convert_w<<<(HID * HID + 255) / 256, 256>>>(W);

    dim3 ggrid(HID / 64, (NN + 127) / 128);
    gemm_mma<<<ggrid, 256, SM_SZ>>>(att_src, att_dst);

    edge_ea<<<(EE + 255) / 256, 256>>>(ei, eattr);
    aggregate<<<(NN + 3) / 4, 256>>>(x, bias, gamma, beta, out);
}

// round 9
// speedup vs baseline: 2.1153x; 1.2009x over previous
#include <cuda_runtime.h>
#include <cuda_bf16.h>
#include <cstdint>

#define NN 50000
#define EE 800000
#define HID 256
#define HEADS 8
#define CPH 32
#define EDIM 64

// ---------------- scratch ----------------
__device__ __nv_bfloat16  g_xpb [(size_t)NN * HID];  // x @ W (bf16, messages only)
__device__ float          g_ea  [(size_t)EE * HEADS];
__device__ float          g_asrc[(size_t)NN * HEADS];
__device__ float          g_adst[(size_t)NN * HEADS];
__device__ float          g_watt[EDIM * HEADS];
__device__ int            g_deg [NN];
__device__ int            g_start[NN];
__device__ int            g_cur [NN];
__device__ int            g_csr_src[EE];
__device__ int            g_total;
__device__ __nv_bfloat16  g_xhi[(size_t)NN * HID];
__device__ __nv_bfloat16  g_xlo[(size_t)NN * HID];
__device__ __nv_bfloat16  g_whi[HID * HID];   // [n][k] = W[k][n]
__device__ __nv_bfloat16  g_wlo[HID * HID];

// ---------------- zero counters ----------------
__global__ void zero_deg() {
    int i = blockIdx.x * blockDim.x + threadIdx.x;
    if (i < NN) g_deg[i] = 0;
    if (i == 0) g_total = 0;
}

// ---------------- fold W_e with att_edge ----------------
__global__ void compute_watt(const float* __restrict__ W_e,
                             const float* __restrict__ att_edge) {
    int i = threadIdx.x;              // 512 threads
    int d = i >> 3, h = i & 7;
    float s = 0.f;
    #pragma unroll
    for (int c = 0; c < CPH; c++)
        s += W_e[d * (HEADS * CPH) + h * CPH + c] * att_edge[h * CPH + c];
    g_watt[d * HEADS + h] = s;
}

// ---------------- CSR build ----------------
__global__ void count_deg(const int* __restrict__ ei) {
    int e = blockIdx.x * blockDim.x + threadIdx.x;
    if (e < EE) atomicAdd(&g_deg[ei[EE + e]], 1);
}

__global__ void reserve_csr() {
    int n = blockIdx.x * blockDim.x + threadIdx.x;
    int lane = threadIdx.x & 31;
    int d = (n < NN) ? g_deg[n] : 0;
    int incl = d;
    #pragma unroll
    for (int o = 1; o < 32; o <<= 1) {
        int v = __shfl_up_sync(0xffffffffu, incl, o);
        if (lane >= o) incl += v;
    }
    int wtotal = __shfl_sync(0xffffffffu, incl, 31);
    int base = 0;
    if (lane == 31) base = atomicAdd(&g_total, wtotal);
    base = __shfl_sync(0xffffffffu, base, 31);
    int start = base + incl - d;
    if (n < NN) { g_start[n] = start; g_cur[n] = start; }
}

// ---------------- fp32 -> bf16 hi/lo split ----------------
__global__ void convert_x(const float* __restrict__ x) {
    size_t i = ((size_t)blockIdx.x * blockDim.x + threadIdx.x) * 4;
    if (i >= (size_t)NN * HID) return;
    float4 v = *(const float4*)(x + i);
    __nv_bfloat16 h0 = __float2bfloat16(v.x);
    __nv_bfloat16 h1 = __float2bfloat16(v.y);
    __nv_bfloat16 h2 = __float2bfloat16(v.z);
    __nv_bfloat16 h3 = __float2bfloat16(v.w);
    __nv_bfloat162 hi0; hi0.x = h0; hi0.y = h1;
    __nv_bfloat162 hi1; hi1.x = h2; hi1.y = h3;
    __nv_bfloat162 lo0, lo1;
    lo0.x = __float2bfloat16(v.x - __bfloat162float(h0));
    lo0.y = __float2bfloat16(v.y - __bfloat162float(h1));
    lo1.x = __float2bfloat16(v.z - __bfloat162float(h2));
    lo1.y = __float2bfloat16(v.w - __bfloat162float(h3));
    *(__nv_bfloat162*)(g_xhi + i)     = hi0;
    *(__nv_bfloat162*)(g_xhi + i + 2) = hi1;
    *(__nv_bfloat162*)(g_xlo + i)     = lo0;
    *(__nv_bfloat162*)(g_xlo + i + 2) = lo1;
}

__global__ void convert_w(const float* __restrict__ W) {
    int i = blockIdx.x * blockDim.x + threadIdx.x;  // 65536
    if (i >= HID * HID) return;
    int n = i >> 8, k = i & 255;
    float v = W[k * HID + n];                        // transpose: B[n][k] = W[k][n]
    __nv_bfloat16 hi = __float2bfloat16(v);
    g_whi[i] = hi;
    g_wlo[i] = __float2bfloat16(v - __bfloat162float(hi));
}

// ================ mma.sync bf16 GEMM (compute_103-legal tensor path) =======
__device__ __forceinline__ void ldsm_x4(uint32_t addr, uint32_t& r0, uint32_t& r1,
                                        uint32_t& r2, uint32_t& r3) {
    asm volatile("ldmatrix.sync.aligned.m8n8.x4.shared.b16 {%0,%1,%2,%3}, [%4];"
                 : "=r"(r0), "=r"(r1), "=r"(r2), "=r"(r3) : "r"(addr));
}
__device__ __forceinline__ void mma_bf16(float* c, const uint32_t* a,
                                         uint32_t b0, uint32_t b1) {
    asm volatile(
        "mma.sync.aligned.m16n8k16.row.col.f32.bf16.bf16.f32 "
        "{%0,%1,%2,%3}, {%4,%5,%6,%7}, {%8,%9}, {%0,%1,%2,%3};"
        : "+f"(c[0]), "+f"(c[1]), "+f"(c[2]), "+f"(c[3])
        : "r"(a[0]), "r"(a[1]), "r"(a[2]), "r"(a[3]), "r"(b0), "r"(b1));
}
__device__ __forceinline__ uint32_t smem_u32(const void* p) {
    uint32_t a;
    asm("{ .reg .u64 t; cvta.to.shared.u64 t, %1; cvt.u32.u64 %0, t; }"
        : "=r"(a) : "l"(p));
    return a;
}

// SMEM layout (dynamic): swizzled tiles, 128B rows of 8x16B chunks
#define SM_AHI  0
#define SM_ALO  16384
#define SM_BHI  32768
#define SM_BLO  40960
#define SM_ATTS 49152
#define SM_ATTD 49408
#define SM_SZ   49664
#define SWO(row, c) ((uint32_t)((row) * 128 + (((c) ^ ((row) & 7)) << 4)))

__global__ __launch_bounds__(256, 2) void gemm_mma(const float* __restrict__ att_src,
                                                   const float* __restrict__ att_dst) {
    extern __shared__ char smem[];
    uint32_t sb = smem_u32(smem);
    int tid = threadIdx.x;
    int wid = tid >> 5;
    int lane = tid & 31;
    int bm = blockIdx.y * 128;
    int bn = blockIdx.x * 64;
    int mrow0 = (wid & 3) * 32;
    int ncol0 = (wid >> 2) * 32;

    float* satts = (float*)(smem + SM_ATTS);
    float* sattd = (float*)(smem + SM_ATTD);
    if (tid < 64) {
        satts[tid] = att_src[bn + tid];
        sattd[tid] = att_dst[bn + tid];
    }

    float acc[2][4][4];
    #pragma unroll
    for (int ma = 0; ma < 2; ma++)
        #pragma unroll
        for (int nb = 0; nb < 4; nb++)
            #pragma unroll
            for (int j = 0; j < 4; j++) acc[ma][nb][j] = 0.f;

    #pragma unroll 1
    for (int kc = 0; kc < 4; kc++) {
        // ---- stage A (128x64, hi+lo) ----
        #pragma unroll
        for (int j = 0; j < 4; j++) {
            int i = tid + j * 256;
            int row = i >> 3, c = i & 7;
            uint32_t off = SWO(row, c);
            int rg = bm + row;
            uint4 vh = make_uint4(0, 0, 0, 0), vl = make_uint4(0, 0, 0, 0);
            if (rg < NN) {
                const __nv_bfloat16* ph = g_xhi + ((size_t)rg << 8) + kc * 64 + c * 8;
                const __nv_bfloat16* pl = g_xlo + ((size_t)rg << 8) + kc * 64 + c * 8;
                vh = *(const uint4*)ph;
                vl = *(const uint4*)pl;
            }
            *(uint4*)(smem + SM_AHI + off) = vh;
            *(uint4*)(smem + SM_ALO + off) = vl;
        }
        // ---- stage B (64x64, hi+lo), rows are n, cols are k ----
        #pragma unroll
        for (int j = 0; j < 2; j++) {
            int i = tid + j * 256;
            int n = i >> 3, c = i & 7;
            uint32_t off = SWO(n, c);
            const __nv_bfloat16* ph = g_whi + ((size_t)(bn + n) << 8) + kc * 64 + c * 8;
            const __nv_bfloat16* pl = g_wlo + ((size_t)(bn + n) << 8) + kc * 64 + c * 8;
            *(uint4*)(smem + SM_BHI + off) = *(const uint4*)ph;
            *(uint4*)(smem + SM_BLO + off) = *(const uint4*)pl;
        }
        __syncthreads();

        #pragma unroll
        for (int ks = 0; ks < 4; ks++) {
            uint32_t ahi[2][4], alo[2][4];
            #pragma unroll
            for (int ma = 0; ma < 2; ma++) {
                int row = mrow0 + ma * 16 + (lane & 15);
                int c = ks * 2 + (lane >> 4);
                uint32_t off = SWO(row, c);
                ldsm_x4(sb + SM_AHI + off, ahi[ma][0], ahi[ma][1], ahi[ma][2], ahi[ma][3]);
                ldsm_x4(sb + SM_ALO + off, alo[ma][0], alo[ma][1], alo[ma][2], alo[ma][3]);
            }
            uint32_t bhi[4][2], blo[4][2];
            #pragma unroll
            for (int nb2 = 0; nb2 < 2; nb2++) {
                int n = ncol0 + nb2 * 16 + (lane & 7) + ((lane & 16) >> 1);
                int c = ks * 2 + ((lane >> 3) & 1);
                uint32_t off = SWO(n, c);
                ldsm_x4(sb + SM_BHI + off, bhi[nb2 * 2][0], bhi[nb2 * 2][1],
                        bhi[nb2 * 2 + 1][0], bhi[nb2 * 2 + 1][1]);
                ldsm_x4(sb + SM_BLO + off, blo[nb2 * 2][0], blo[nb2 * 2][1],
                        blo[nb2 * 2 + 1][0], blo[nb2 * 2 + 1][1]);
            }
            #pragma unroll
            for (int ma = 0; ma < 2; ma++)
                #pragma unroll
                for (int nb = 0; nb < 4; nb++) {
                    mma_bf16(acc[ma][nb], ahi[ma], bhi[nb][0], bhi[nb][1]);
                    mma_bf16(acc[ma][nb], ahi[ma], blo[nb][0], blo[nb][1]);
                    mma_bf16(acc[ma][nb], alo[ma], bhi[nb][0], bhi[nb][1]);
                }
        }
        __syncthreads();
    }

    // ---- epilogue: store xp (bf16) + fused a_src/a_dst (one head per warp) ----
    int head = (bn + ncol0) >> 5;
    #pragma unroll
    for (int ma = 0; ma < 2; ma++) {
        int row0 = bm + mrow0 + ma * 16 + (lane >> 2);
        int row1 = row0 + 8;
        float ps0 = 0.f, pd0 = 0.f, ps1 = 0.f, pd1 = 0.f;
        #pragma unroll
        for (int nb = 0; nb < 4; nb++) {
            int colt = ncol0 + nb * 8 + (lane & 3) * 2;   // col within 64-tile
            float c0 = acc[ma][nb][0], c1 = acc[ma][nb][1];
            float c2 = acc[ma][nb][2], c3 = acc[ma][nb][3];
            if (row0 < NN) {
                __nv_bfloat162 p; p.x = __float2bfloat16(c0); p.y = __float2bfloat16(c1);
                *(__nv_bfloat162*)(g_xpb + (size_t)row0 * HID + bn + colt) = p;
            }
            if (row1 < NN) {
                __nv_bfloat162 p; p.x = __float2bfloat16(c2); p.y = __float2bfloat16(c3);
                *(__nv_bfloat162*)(g_xpb + (size_t)row1 * HID + bn + colt) = p;
            }
            float as0 = satts[colt], as1 = satts[colt + 1];
            float ad0 = sattd[colt], ad1 = sattd[colt + 1];
            ps0 += c0 * as0 + c1 * as1;
            pd0 += c0 * ad0 + c1 * ad1;
            ps1 += c2 * as0 + c3 * as1;
            pd1 += c2 * ad0 + c3 * ad1;
        }
        #pragma unroll
        for (int o = 1; o <= 2; o <<= 1) {
            ps0 += __shfl_xor_sync(0xffffffffu, ps0, o);
            pd0 += __shfl_xor_sync(0xffffffffu, pd0, o);
            ps1 += __shfl_xor_sync(0xffffffffu, ps1, o);
            pd1 += __shfl_xor_sync(0xffffffffu, pd1, o);
        }
        if ((lane & 3) == 0) {
            if (row0 < NN) {
                g_asrc[(size_t)row0 * HEADS + head] = ps0;
                g_adst[(size_t)row0 * HEADS + head] = pd0;
            }
            if (row1 < NN) {
                g_asrc[(size_t)row1 * HEADS + head] = ps1;
                g_adst[(size_t)row1 * HEADS + head] = pd1;
            }
        }
    }
}

// -------- edge pass: logits -> leakyrelu -> exp + fused CSR scatter --------
__global__ __launch_bounds__(256) void edge_ea(const int* __restrict__ ei,
                                               const float* __restrict__ eattr) {
    __shared__ float4 ws4[EDIM * 2];       // [d*2] = heads0-3, [d*2+1] = heads4-7
    for (int i = threadIdx.x; i < EDIM * 2; i += blockDim.x)
        ws4[i] = ((const float4*)g_watt)[i];
    __syncthreads();
    int e = blockIdx.x * blockDim.x + threadIdx.x;
    if (e >= EE) return;
    int src = ei[e];
    int dst = ei[EE + e];

    const float4* as4 = (const float4*)(g_asrc + (size_t)src * HEADS);
    const float4* ad4 = (const float4*)(g_adst + (size_t)dst * HEADS);
    float4 as0 = as4[0], as1 = as4[1];
    float4 ad0 = ad4[0], ad1 = ad4[1];

    float4 accA = make_float4(0.f, 0.f, 0.f, 0.f);
    float4 accB = make_float4(0.f, 0.f, 0.f, 0.f);

    const float4* ea4 = (const float4*)(eattr + (size_t)e * EDIM);
    #pragma unroll
    for (int d4 = 0; d4 < EDIM / 4; d4++) {
        float4 v = ea4[d4];
        int d = d4 * 4;
        float4 w;
        w = ws4[(d + 0) * 2];     accA.x += v.x * w.x; accA.y += v.x * w.y; accA.z += v.x * w.z; accA.w += v.x * w.w;
        w = ws4[(d + 0) * 2 + 1]; accB.x += v.x * w.x; accB.y += v.x * w.y; accB.z += v.x * w.z; accB.w += v.x * w.w;
        w = ws4[(d + 1) * 2];     accA.x += v.y * w.x; accA.y += v.y * w.y; accA.z += v.y * w.z; accA.w += v.y * w.w;
        w = ws4[(d + 1) * 2 + 1]; accB.x += v.y * w.x; accB.y += v.y * w.y; accB.z += v.y * w.z; accB.w += v.y * w.w;
        w = ws4[(d + 2) * 2];     accA.x += v.z * w.x; accA.y += v.z * w.y; accA.z += v.z * w.z; accA.w += v.z * w.w;
        w = ws4[(d + 2) * 2 + 1]; accB.x += v.z * w.x; accB.y += v.z * w.y; accB.z += v.z * w.z; accB.w += v.z * w.w;
        w = ws4[(d + 3) * 2];     accA.x += v.w * w.x; accA.y += v.w * w.y; accA.z += v.w * w.z; accA.w += v.w * w.w;
        w = ws4[(d + 3) * 2 + 1]; accB.x += v.w * w.x; accB.y += v.w * w.y; accB.z += v.w * w.z; accB.w += v.w * w.w;
    }

    float a[HEADS];
    a[0] = as0.x + ad0.x + accA.x;
    a[1] = as0.y + ad0.y + accA.y;
    a[2] = as0.z + ad0.z + accA.z;
    a[3] = as0.w + ad0.w + accA.w;
    a[4] = as1.x + ad1.x + accB.x;
    a[5] = as1.y + ad1.y + accB.y;
    a[6] = as1.z + ad1.z + accB.z;
    a[7] = as1.w + ad1.w + accB.w;

    #pragma unroll
    for (int h = 0; h < HEADS; h++) {
        float al = a[h];
        al = (al > 0.f) ? al : 0.2f * al;   // LeakyReLU
        a[h] = __expf(al);                  // softmax is shift-invariant
    }
    int pos = atomicAdd(&g_cur[dst], 1);    // fused CSR slot reservation
    g_csr_src[pos] = src;
    float4* out = (float4*)(g_ea + (size_t)pos * HEADS);
    out[0] = make_float4(a[0], a[1], a[2], a[3]);
    out[1] = make_float4(a[4], a[5], a[6], a[7]);
}

// -------- aggregate: 1 warp/node, bf16 xp gather, residual + LN -------------
__global__ __launch_bounds__(256) void aggregate(const float* __restrict__ x,
                                                 const float* __restrict__ bias,
                                                 const float* __restrict__ gamma,
                                                 const float* __restrict__ beta,
                                                 float* __restrict__ out) {
    int node = blockIdx.x * 8 + (threadIdx.x >> 5);
    int lane = threadIdx.x & 31;
    if (node >= NN) return;
    int start = g_start[node];
    int deg   = g_deg[node];
    int myhead = lane >> 2;          // channels lane*8 .. lane*8+7 are all in this head
    int epair = myhead >> 1;         // ea float2 pair index for my head

    float accf[8];
    #pragma unroll
    for (int k = 0; k < 8; k++) accf[k] = 0.f;
    float2 den2 = make_float2(0.f, 0.f);   // heads (lane&3)*2, +1

    int i0 = 0;
    for (; i0 + 8 <= deg; i0 += 8) {
        int p0 = start + i0;
        int srcs = (lane < 8) ? g_csr_src[p0 + lane] : 0;
        float2 eav = *(const float2*)(g_ea + (size_t)(p0 + (lane >> 2)) * HEADS + (lane & 3) * 2);
        den2.x += eav.x;
        den2.y += eav.y;
        #pragma unroll
        for (int j = 0; j < 8; j++) {
            int src = __shfl_sync(0xffffffffu, srcs, j);
            float ex = __shfl_sync(0xffffffffu, eav.x, j * 4 + epair);
            float ey = __shfl_sync(0xffffffffu, eav.y, j * 4 + epair);
            float eh = (myhead & 1) ? ey : ex;
            uint4 v = *(const uint4*)(g_xpb + (size_t)src * HID + lane * 8);
            float2 f0 = __bfloat1622float2(*(__nv_bfloat162*)&v.x);
            float2 f1 = __bfloat1622float2(*(__nv_bfloat162*)&v.y);
            float2 f2 = __bfloat1622float2(*(__nv_bfloat162*)&v.z);
            float2 f3 = __bfloat1622float2(*(__nv_bfloat162*)&v.w);
            accf[0] += eh * f0.x; accf[1] += eh * f0.y;
            accf[2] += eh * f1.x; accf[3] += eh * f1.y;
            accf[4] += eh * f2.x; accf[5] += eh * f2.y;
            accf[6] += eh * f3.x; accf[7] += eh * f3.y;
        }
    }
    if (i0 < deg) {
        int rem = deg - i0;
        int p0 = start + i0;
        int srcs = (lane < rem && lane < 8) ? g_csr_src[p0 + lane] : 0;
        float2 eav = make_float2(0.f, 0.f);
        if ((lane >> 2) < rem)
            eav = *(const float2*)(g_ea + (size_t)(p0 + (lane >> 2)) * HEADS + (lane & 3) * 2);
        den2.x += eav.x;
        den2.y += eav.y;
        for (int j = 0; j < rem; j++) {
            int src = __shfl_sync(0xffffffffu, srcs, j);
            float ex = __shfl_sync(0xffffffffu, eav.x, j * 4 + epair);
            float ey = __shfl_sync(0xffffffffu, eav.y, j * 4 + epair);
            float eh = (myhead & 1) ? ey : ex;
            uint4 v = *(const uint4*)(g_xpb + (size_t)src * HID + lane * 8);
            float2 f0 = __bfloat1622float2(*(__nv_bfloat162*)&v.x);
            float2 f1 = __bfloat1622float2(*(__nv_bfloat162*)&v.y);
            float2 f2 = __bfloat1622float2(*(__nv_bfloat162*)&v.z);
            float2 f3 = __bfloat1622float2(*(__nv_bfloat162*)&v.w);
            accf[0] += eh * f0.x; accf[1] += eh * f0.y;
            accf[2] += eh * f1.x; accf[3] += eh * f1.y;
            accf[4] += eh * f2.x; accf[5] += eh * f2.y;
            accf[6] += eh * f3.x; accf[7] += eh * f3.y;
        }
    }

    // den: reduce over edge-slot lane bits (2,3,4); lanes grouped by (lane&3)
    #pragma unroll
    for (int o = 4; o < 32; o <<= 1) {
        den2.x += __shfl_xor_sync(0xffffffffu, den2.x, o);
        den2.y += __shfl_xor_sync(0xffffffffu, den2.y, o);
    }
    float dx = __shfl_sync(0xffffffffu, den2.x, epair);  // head myhead&~1
    float dy = __shfl_sync(0xffffffffu, den2.y, epair);  // head myhead|1
    float den = (myhead & 1) ? dy : dx;
    float inv = 1.f / (den + 1e-16f);

    // residual + bias
    const float4* x4 = (const float4*)(x + (size_t)node * HID + lane * 8);
    const float4* b4 = (const float4*)(bias + lane * 8);
    float4 xa = x4[0], xb = x4[1];
    float4 ba = b4[0], bb = b4[1];
    float va[8];
    va[0] = xa.x + accf[0] * inv + ba.x;
    va[1] = xa.y + accf[1] * inv + ba.y;
    va[2] = xa.z + accf[2] * inv + ba.z;
    va[3] = xa.w + accf[3] * inv + ba.w;
    va[4] = xb.x + accf[4] * inv + bb.x;
    va[5] = xb.y + accf[5] * inv + bb.y;
    va[6] = xb.z + accf[6] * inv + bb.z;
    va[7] = xb.w + accf[7] * inv + bb.w;

    float s = 0.f, q = 0.f;
    #pragma unroll
    for (int k = 0; k < 8; k++) { s += va[k]; q += va[k] * va[k]; }
    #pragma unroll
    for (int o = 16; o > 0; o >>= 1) {
        s += __shfl_xor_sync(0xffffffffu, s, o);
        q += __shfl_xor_sync(0xffffffffu, q, o);
    }
    float mu = s * (1.f / HID);
    float var = q * (1.f / HID) - mu * mu;
    float rstd = rsqrtf(var + 1e-5f);

    const float4* g4 = (const float4*)(gamma + lane * 8);
    const float4* e4 = (const float4*)(beta + lane * 8);
    float4 ga = g4[0], gb = g4[1];
    float4 be = e4[0], bf = e4[1];
    float4 oa, ob;
    oa.x = (va[0] - mu) * rstd * ga.x + be.x;
    oa.y = (va[1] - mu) * rstd * ga.y + be.y;
    oa.z = (va[2] - mu) * rstd * ga.z + be.z;
    oa.w = (va[3] - mu) * rstd * ga.w + be.w;
    ob.x = (va[4] - mu) * rstd * gb.x + bf.x;
    ob.y = (va[5] - mu) * rstd * gb.y + bf.y;
    ob.z = (va[6] - mu) * rstd * gb.z + bf.z;
    ob.w = (va[7] - mu) * rstd * gb.w + bf.w;

    float4* o4 = (float4*)(out + (size_t)node * HID + lane * 8);
    o4[0] = oa;
    o4[1] = ob;
}

// ---------------- launch ----------------
extern "C" void kernel_launch(void* const* d_in, const int* in_sizes, int n_in,
                              void* d_out, int out_size) {
    const float* x        = (const float*)d_in[0];
    const int*   ei       = (const int*)  d_in[1];
    const float* eattr    = (const float*)d_in[2];
    const float* W        = (const float*)d_in[3];
    const float* W_e      = (const float*)d_in[4];
    const float* att_src  = (const float*)d_in[5];
    const float* att_dst  = (const float*)d_in[6];
    const float* att_edge = (const float*)d_in[7];
    const float* bias     = (const float*)d_in[8];
    const float* gamma    = (const float*)d_in[9];
    const float* beta     = (const float*)d_in[10];
    float* out = (float*)d_out;

    cudaFuncSetAttribute(gemm_mma, cudaFuncAttributeMaxDynamicSharedMemorySize, SM_SZ);

    zero_deg<<<(NN + 255) / 256, 256>>>();
    compute_watt<<<1, EDIM * HEADS>>>(W_e, att_edge);
    count_deg<<<(EE + 255) / 256, 256>>>(ei);
    reserve_csr<<<(NN + 255) / 256, 256>>>();

    convert_x<<<(NN * HID / 4 + 255) / 256, 256>>>(x);
    convert_w<<<(HID * HID + 255) / 256, 256>>>(W);

    dim3 ggrid(HID / 64, (NN + 127) / 128);
    gemm_mma<<<ggrid, 256, SM_SZ>>>(att_src, att_dst);

    edge_ea<<<(EE + 255) / 256, 256>>>(ei, eattr);
    aggregate<<<(NN + 7) / 8, 256>>>(x, bias, gamma, beta, out);
}